// round 7
// baseline (speedup 1.0000x reference)
#include <cuda_runtime.h>
#include <cuda_bf16.h>
#include <math.h>
#include <stdint.h>

// Problem constants
#define Bq   4
#define Tq   2048
#define Cq   1024
#define NH   16
#define HD   64
#define C3   (3 * Cq)          // 3072
#define MQ   (Bq * Tq)         // 8192 rows

// ---------------------------------------------------------------------------
// Scratch (device globals; no runtime allocation allowed)
// ---------------------------------------------------------------------------
__device__ float g_qkv[(size_t)MQ * C3];   // [B*T, 3C]
__device__ float g_y  [(size_t)MQ * Cq];   // [B*T, C]

// ---------------------------------------------------------------------------
// bf16 split helpers
// ---------------------------------------------------------------------------
__device__ __forceinline__ uint32_t bf16_rne_bits(float x) {   // RNE-rounded hi, as fp32 bits
    uint32_t u = __float_as_uint(x);
    return (u + 0x7FFFu + ((u >> 16) & 1u)) & 0xFFFF0000u;
}
__device__ __forceinline__ uint32_t bf16pack(float lo_elem, float hi_elem) {  // lo_elem -> low 16 bits
    uint32_t r;
    asm("cvt.rn.bf16x2.f32 %0, %1, %2;" : "=r"(r) : "f"(hi_elem), "f"(lo_elem));
    return r;
}
#define ASF(u) __uint_as_float(u)

#define MMA_BF16(d, av, bv)                                                    \
  asm volatile("mma.sync.aligned.m16n8k16.row.col.f32.bf16.bf16.f32 "          \
      "{%0,%1,%2,%3}, {%4,%5,%6,%7}, {%8,%9}, {%0,%1,%2,%3};"                  \
      : "+f"((d)[0]), "+f"((d)[1]), "+f"((d)[2]), "+f"((d)[3])                 \
      : "r"((av)[0]), "r"((av)[1]), "r"((av)[2]), "r"((av)[3]),                \
        "r"((bv)[0]), "r"((bv)[1]))

// ---------------------------------------------------------------------------
// Warp-MMA GEMM: C[M,N] = A[M,K] @ B[K,N] + bias[N]
// bf16 hi/lo split (3 products), fp32 accum. 128x128 CTA tile, 8 warps,
// 64x32 per warp, K chunks of 32. M,N mult of 128; K mult of 32.
// ---------------------------------------------------------------------------
#define KC  32               // K chunk
#define SP  20               // padded kpair-row stride (words) -> conflict-free frags
// dynamic SMEM (words):
//   Ahi[128*20] Alo[128*20] Bhi[128*20] Blo[128*20] stage_f32[32*132]
#define W_AHI 0
#define W_ALO 2560
#define W_BHI 5120
#define W_BLO 7680
#define W_STG 10240
#define GSM_WORDS (10240 + 32 * 132)
#define GSM_BYTES (GSM_WORDS * 4)      // 57856

__global__ __launch_bounds__(256, 2)
void gemm_mma_kernel(const float* __restrict__ A, const float* __restrict__ B,
                     const float* __restrict__ bias, float* __restrict__ C,
                     int M, int N, int K)
{
    extern __shared__ uint32_t sm[];
    uint32_t* Ahi = sm + W_AHI;
    uint32_t* Alo = sm + W_ALO;
    uint32_t* Bhi = sm + W_BHI;
    uint32_t* Blo = sm + W_BLO;
    float*    stg = (float*)(sm + W_STG);

    const int tid  = threadIdx.x;
    const int lane = tid & 31;
    const int w    = tid >> 5;
    const int m0   = blockIdx.y * 128;
    const int n0   = blockIdx.x * 128;
    const int mb   = (w & 1) * 64;       // warp m-offset in tile
    const int nb   = (w >> 1) * 32;      // warp n-offset in tile
    const int g    = lane >> 2;          // 0..7
    const int q    = lane & 3;           // 0..3

    float acc[4][4][4];
#pragma unroll
    for (int mt = 0; mt < 4; mt++)
#pragma unroll
        for (int nt = 0; nt < 4; nt++)
#pragma unroll
            for (int i = 0; i < 4; i++) acc[mt][nt][i] = 0.0f;

    const int nchunks = K / KC;
    for (int c = 0; c < nchunks; c++) {
        const int k0 = c * KC;
        __syncthreads();                 // prev compute done before overwrite

        // ---- A tile 128m x 32k fp32 -> Ahi/Alo [m][kpair], stride SP ----
#pragma unroll
        for (int p = 0; p < 4; p++) {
            int linear = tid * 4 + p * 1024;   // 4096 floats
            int row = linear >> 5;             // m
            int col = linear & 31;             // k, mult of 4
            float4 v = *(const float4*)&A[(size_t)(m0 + row) * K + k0 + col];
            uint32_t hx = bf16_rne_bits(v.x), hy = bf16_rne_bits(v.y);
            uint32_t hz = bf16_rne_bits(v.z), hw = bf16_rne_bits(v.w);
            int kp = col >> 1;
            Ahi[row * SP + kp + 0] = (hx >> 16) | (hy & 0xFFFF0000u);
            Ahi[row * SP + kp + 1] = (hz >> 16) | (hw & 0xFFFF0000u);
            Alo[row * SP + kp + 0] = bf16pack(v.x - ASF(hx), v.y - ASF(hy));
            Alo[row * SP + kp + 1] = bf16pack(v.z - ASF(hz), v.w - ASF(hw));
        }
        // ---- B tile 32k x 128n fp32 -> staging (coalesced) ----
#pragma unroll
        for (int p = 0; p < 4; p++) {
            int linear = tid * 4 + p * 1024;
            int row = linear >> 7;             // k 0..31
            int col = linear & 127;            // n
            *(float4*)&stg[row * 132 + col] =
                *(const float4*)&B[(size_t)(k0 + row) * N + n0 + col];
        }
        __syncthreads();

        // ---- B transpose+convert: staging -> Bhi/Blo [n][kpair] ----
        {
            int kp  = tid >> 4;                // 0..15
            int nlo = tid & 15;
#pragma unroll
            for (int j = 0; j < 8; j++) {
                int n = nlo + 16 * j;
                float x0 = stg[(2 * kp + 0) * 132 + n];
                float x1 = stg[(2 * kp + 1) * 132 + n];
                uint32_t h0 = bf16_rne_bits(x0), h1 = bf16_rne_bits(x1);
                Bhi[n * SP + kp] = (h0 >> 16) | (h1 & 0xFFFF0000u);
                Blo[n * SP + kp] = bf16pack(x0 - ASF(h0), x1 - ASF(h1));
            }
        }
        __syncthreads();

        // ---- compute: 2 k16-steps x 3 split combos x 16 mma tiles ----
#pragma unroll
        for (int ks = 0; ks < 2; ks++) {
            const int kp0 = ks * 8;
#pragma unroll
            for (int combo = 0; combo < 3; combo++) {
                const uint32_t* As = (combo == 2) ? Alo : Ahi;
                const uint32_t* Bs = (combo == 1) ? Blo : Bhi;
                uint32_t a[4][4], b[4][2];
#pragma unroll
                for (int mt = 0; mt < 4; mt++) {
                    int base = (mb + mt * 16 + g) * SP + kp0 + q;
                    a[mt][0] = As[base];
                    a[mt][1] = As[base + 8 * SP];
                    a[mt][2] = As[base + 4];
                    a[mt][3] = As[base + 8 * SP + 4];
                }
#pragma unroll
                for (int nt = 0; nt < 4; nt++) {
                    int base = (nb + nt * 8 + g) * SP + kp0 + q;
                    b[nt][0] = Bs[base];
                    b[nt][1] = Bs[base + 4];
                }
#pragma unroll
                for (int mt = 0; mt < 4; mt++)
#pragma unroll
                    for (int nt = 0; nt < 4; nt++)
                        MMA_BF16(acc[mt][nt], a[mt], b[nt]);
            }
        }
    }

    // ---- epilogue: direct STG with fused bias ----
#pragma unroll
    for (int mt = 0; mt < 4; mt++) {
        int row = m0 + mb + mt * 16 + g;
#pragma unroll
        for (int nt = 0; nt < 4; nt++) {
            int col = n0 + nb + nt * 8 + 2 * q;
            float2 bv = *(const float2*)&bias[col];
            float2 o0 = make_float2(acc[mt][nt][0] + bv.x, acc[mt][nt][1] + bv.y);
            float2 o1 = make_float2(acc[mt][nt][2] + bv.x, acc[mt][nt][3] + bv.y);
            *(float2*)&C[(size_t)row * N + col]       = o0;
            *(float2*)&C[(size_t)(row + 8) * N + col] = o1;
        }
    }
}

// ---------------------------------------------------------------------------
// Flash-attention (fp32, causal) — unchanged, known-good
// ---------------------------------------------------------------------------
__device__ __forceinline__ int tswz(int d, int q)
{
    return d * 64 + ((((q >> 2) ^ ((d >> 2) & 15)) << 2) | (q & 3));
}

__global__ __launch_bounds__(256, 2)
void attn_kernel(const float* __restrict__ qkv, float* __restrict__ y)
{
    __shared__ float Qt[64 * 64];
    __shared__ float KP[64 * 64];
    __shared__ float Vs[64 * 64];

    const int tid = threadIdx.x;
    const int tx  = tid & 15;
    const int ty  = tid >> 4;
    const int bh  = blockIdx.y;
    const int b   = bh >> 4;
    const int h   = bh & 15;
    const int qt  = blockIdx.x;
    const int q0  = qt * 64;
    const float scale = 0.125f;

    const float* qbase = qkv + (size_t)b * Tq * C3 + h * HD;
    const float* kbase = qbase + Cq;
    const float* vbase = qbase + 2 * Cq;

#pragma unroll
    for (int p = 0; p < 4; p++) {
        int linear = tid * 4 + p * 1024;
        int q = linear / 64;
        int d = linear % 64;
        float4 v = *(const float4*)&qbase[(size_t)(q0 + q) * C3 + d];
        Qt[tswz(d + 0, q)] = v.x;
        Qt[tswz(d + 1, q)] = v.y;
        Qt[tswz(d + 2, q)] = v.z;
        Qt[tswz(d + 3, q)] = v.w;
    }

    float m[4], l[4], acc[4][4];
#pragma unroll
    for (int r = 0; r < 4; r++) {
        m[r] = -1e30f; l[r] = 0.0f;
#pragma unroll
        for (int j = 0; j < 4; j++) acc[r][j] = 0.0f;
    }

    for (int kt = 0; kt <= qt; kt++) {
        const int k0 = kt * 64;
        __syncthreads();

#pragma unroll
        for (int p = 0; p < 4; p++) {
            int linear = tid * 4 + p * 1024;
            int kk = linear / 64;
            int d  = linear % 64;
            float4 kv = *(const float4*)&kbase[(size_t)(k0 + kk) * C3 + d];
            KP[tswz(d + 0, kk)] = kv.x;
            KP[tswz(d + 1, kk)] = kv.y;
            KP[tswz(d + 2, kk)] = kv.z;
            KP[tswz(d + 3, kk)] = kv.w;
            float4 vv = *(const float4*)&vbase[(size_t)(k0 + kk) * C3 + d];
            *(float4*)&Vs[kk * 64 + d] = vv;
        }
        __syncthreads();

        float s[4][4];
#pragma unroll
        for (int r = 0; r < 4; r++)
#pragma unroll
            for (int j = 0; j < 4; j++) s[r][j] = 0.0f;

#pragma unroll 8
        for (int d = 0; d < 64; d++) {
            float4 qa = *(const float4*)&Qt[tswz(d, 4 * ty)];
            float4 kb = *(const float4*)&KP[tswz(d, 4 * tx)];
            float av[4] = {qa.x, qa.y, qa.z, qa.w};
            float bv[4] = {kb.x, kb.y, kb.z, kb.w};
#pragma unroll
            for (int r = 0; r < 4; r++)
#pragma unroll
                for (int j = 0; j < 4; j++)
                    s[r][j] = fmaf(av[r], bv[j], s[r][j]);
        }

#pragma unroll
        for (int r = 0; r < 4; r++)
#pragma unroll
            for (int j = 0; j < 4; j++) {
                s[r][j] *= scale;
                if (kt == qt && (4 * tx + j) > (4 * ty + r)) s[r][j] = -1e30f;
            }

#pragma unroll
        for (int r = 0; r < 4; r++) {
            float rmax = fmaxf(fmaxf(s[r][0], s[r][1]), fmaxf(s[r][2], s[r][3]));
#pragma unroll
            for (int off = 1; off < 16; off <<= 1)
                rmax = fmaxf(rmax, __shfl_xor_sync(0xffffffffu, rmax, off));
            float mnew  = fmaxf(m[r], rmax);
            float alpha = __expf(m[r] - mnew);
            float rsum  = 0.0f;
#pragma unroll
            for (int j = 0; j < 4; j++) {
                s[r][j] = __expf(s[r][j] - mnew);
                rsum += s[r][j];
            }
#pragma unroll
            for (int off = 1; off < 16; off <<= 1)
                rsum += __shfl_xor_sync(0xffffffffu, rsum, off);
            l[r] = l[r] * alpha + rsum;
            m[r] = mnew;
#pragma unroll
            for (int j = 0; j < 4; j++) acc[r][j] *= alpha;
        }

        __syncthreads();

#pragma unroll
        for (int j = 0; j < 4; j++) {
            int kk = 4 * tx + j;
            float4 pv = make_float4(s[0][j], s[1][j], s[2][j], s[3][j]);
            *(float4*)&KP[tswz(kk, 4 * ty)] = pv;
        }
        __syncthreads();

#pragma unroll 8
        for (int kk = 0; kk < 64; kk++) {
            float4 pp = *(const float4*)&KP[tswz(kk, 4 * ty)];
            float4 vv = *(const float4*)&Vs[kk * 64 + 4 * tx];
            float pv[4] = {pp.x, pp.y, pp.z, pp.w};
            float vw[4] = {vv.x, vv.y, vv.z, vv.w};
#pragma unroll
            for (int r = 0; r < 4; r++)
#pragma unroll
                for (int j = 0; j < 4; j++)
                    acc[r][j] = fmaf(pv[r], vw[j], acc[r][j]);
        }
    }

#pragma unroll
    for (int r = 0; r < 4; r++) {
        int q = q0 + 4 * ty + r;
        float inv = 1.0f / l[r];
        float4 o = make_float4(acc[r][0] * inv, acc[r][1] * inv,
                               acc[r][2] * inv, acc[r][3] * inv);
        *(float4*)&y[((size_t)b * Tq + q) * Cq + h * HD + 4 * tx] = o;
    }
}

// ---------------------------------------------------------------------------
// Launch
// ---------------------------------------------------------------------------
extern "C" void kernel_launch(void* const* d_in, const int* in_sizes, int n_in,
                              void* d_out, int out_size)
{
    (void)in_sizes; (void)n_in; (void)out_size;
    const float* x      = (const float*)d_in[0];
    const float* W_attn = (const float*)d_in[1];
    const float* b_attn = (const float*)d_in[2];
    const float* W_proj = (const float*)d_in[3];
    const float* b_proj = (const float*)d_in[4];
    float* out = (float*)d_out;

    float *qkv = nullptr, *y = nullptr;
    cudaGetSymbolAddress((void**)&qkv, g_qkv);
    cudaGetSymbolAddress((void**)&y,   g_y);

    cudaFuncSetAttribute(gemm_mma_kernel,
                         cudaFuncAttributeMaxDynamicSharedMemorySize, GSM_BYTES);

    // 1) qkv = x @ W_attn + b_attn          [8192, 3072]
    gemm_mma_kernel<<<dim3(C3 / 128, MQ / 128), 256, GSM_BYTES>>>(
        x, W_attn, b_attn, qkv, MQ, C3, Cq);
    // 2) y = causal_attention(qkv)          [B, T, C]
    attn_kernel<<<dim3(Tq / 64, Bq * NH), 256>>>(qkv, y);
    // 3) out = y @ W_proj + b_proj          [8192, 1024]
    gemm_mma_kernel<<<dim3(Cq / 128, MQ / 128), 256, GSM_BYTES>>>(
        y, W_proj, b_proj, out, MQ, Cq, Cq);
}

// round 9
// speedup vs baseline: 2.7036x; 2.7036x over previous
#include <cuda_runtime.h>
#include <cuda_bf16.h>
#include <math.h>
#include <stdint.h>

// Problem constants
#define Bq   4
#define Tq   2048
#define Cq   1024
#define NH   16
#define HD   64
#define C3   (3 * Cq)          // 3072
#define MQ   (Bq * Tq)         // 8192 rows

// ---------------------------------------------------------------------------
// Scratch (device globals; no runtime allocation allowed)
// ---------------------------------------------------------------------------
__device__ __align__(128) __nv_bfloat16 g_xh[(size_t)MQ * Cq];
__device__ __align__(128) __nv_bfloat16 g_xl[(size_t)MQ * Cq];
__device__ __align__(128) __nv_bfloat16 g_wqkvT_h[(size_t)C3 * Cq];
__device__ __align__(128) __nv_bfloat16 g_wqkvT_l[(size_t)C3 * Cq];
__device__ __align__(128) __nv_bfloat16 g_wprojT_h[(size_t)Cq * Cq];
__device__ __align__(128) __nv_bfloat16 g_wprojT_l[(size_t)Cq * Cq];
__device__ __align__(128) __nv_bfloat16 g_qkvh[(size_t)MQ * C3];
__device__ __align__(128) __nv_bfloat16 g_qkvl[(size_t)MQ * C3];
__device__ __align__(128) __nv_bfloat16 g_yh[(size_t)MQ * Cq];
__device__ __align__(128) __nv_bfloat16 g_yl[(size_t)MQ * Cq];

// ---------------------------------------------------------------------------
// helpers
// ---------------------------------------------------------------------------
__device__ __forceinline__ uint32_t bf16_rne_bits(float x) {   // RNE hi as fp32 bits
    uint32_t u = __float_as_uint(x);
    return (u + 0x7FFFu + ((u >> 16) & 1u)) & 0xFFFF0000u;
}
__device__ __forceinline__ uint32_t bf16pack(float lo_elem, float hi_elem) {  // lo -> low 16
    uint32_t r;
    asm("cvt.rn.bf16x2.f32 %0, %1, %2;" : "=r"(r) : "f"(hi_elem), "f"(lo_elem));
    return r;
}
#define ASF(u) __uint_as_float(u)

#define MMA_BF16(d, av, bv)                                                    \
  asm volatile("mma.sync.aligned.m16n8k16.row.col.f32.bf16.bf16.f32 "          \
      "{%0,%1,%2,%3}, {%4,%5,%6,%7}, {%8,%9}, {%0,%1,%2,%3};"                  \
      : "+f"((d)[0]), "+f"((d)[1]), "+f"((d)[2]), "+f"((d)[3])                 \
      : "r"((av)[0]), "r"((av)[1]), "r"((av)[2]), "r"((av)[3]),                \
        "r"((bv)[0]), "r"((bv)[1]))

// ---------------------------------------------------------------------------
// cvt kernels: fp32 -> bf16 hi/lo (elementwise, and transposed for weights)
// ---------------------------------------------------------------------------
__global__ void cvt_split_kernel(const float* __restrict__ a,
                                 __nv_bfloat16* __restrict__ hi,
                                 __nv_bfloat16* __restrict__ lo, int n4)
{
    int i = blockIdx.x * 256 + threadIdx.x;
    if (i >= n4) return;
    float4 v = ((const float4*)a)[i];
    uint32_t hx = bf16_rne_bits(v.x), hy = bf16_rne_bits(v.y);
    uint32_t hz = bf16_rne_bits(v.z), hw = bf16_rne_bits(v.w);
    uint32_t* h32 = (uint32_t*)hi;
    uint32_t* l32 = (uint32_t*)lo;
    h32[2 * i + 0] = (hx >> 16) | (hy & 0xFFFF0000u);
    h32[2 * i + 1] = (hz >> 16) | (hw & 0xFFFF0000u);
    l32[2 * i + 0] = bf16pack(v.x - ASF(hx), v.y - ASF(hy));
    l32[2 * i + 1] = bf16pack(v.z - ASF(hz), v.w - ASF(hw));
}

// W[K][N] -> out[N][K] hi/lo
__global__ void cvt_splitT_kernel(const float* __restrict__ w,
                                  __nv_bfloat16* __restrict__ th,
                                  __nv_bfloat16* __restrict__ tl, int K, int N)
{
    __shared__ float t[32][33];
    int tx = threadIdx.x & 31, ty = threadIdx.x >> 5;   // 32 x 8
    int k0 = blockIdx.y * 32, n0 = blockIdx.x * 32;
#pragma unroll
    for (int r = 0; r < 4; r++)
        t[ty + 8 * r][tx] = w[(size_t)(k0 + ty + 8 * r) * N + n0 + tx];
    __syncthreads();
#pragma unroll
    for (int r = 0; r < 4; r++) {
        int n = n0 + ty + 8 * r;
        float v = t[tx][ty + 8 * r];
        uint32_t h = bf16_rne_bits(v);
        th[(size_t)n * K + k0 + tx] = __ushort_as_bfloat16((unsigned short)(h >> 16));
        float rlo = v - ASF(h);
        uint32_t hl = bf16_rne_bits(rlo);
        tl[(size_t)n * K + k0 + tx] = __ushort_as_bfloat16((unsigned short)(hl >> 16));
    }
}

// ---------------------------------------------------------------------------
// Warp-MMA GEMM on pre-split operands.
//  C[M,N] = (Ah+Al)[M,K] @ (Bth+Btl)^T[K,N] + bias
//  A arrays [M][K] bf16 row-major; Bt arrays [N][K] bf16 row-major.
//  128x128 CTA / 8 warps / 64x32 warp tile / K-chunk 64.
//  splitOut=1: write Ch/Cl bf16 split; else fp32 Cf.
// ---------------------------------------------------------------------------
#define SP2 36
// smem words: Ahi 0, Alo 4608, Bhi 9216, Blo 13824; total 18432 (73728 B)
#define G2_BYTES (18432 * 4)

__global__ __launch_bounds__(256, 2)
void gemm_mma2_kernel(const uint32_t* __restrict__ Ah, const uint32_t* __restrict__ Al,
                      const uint32_t* __restrict__ Bth, const uint32_t* __restrict__ Btl,
                      const float* __restrict__ bias, float* __restrict__ Cf,
                      uint32_t* __restrict__ Ch, uint32_t* __restrict__ Cl,
                      int M, int N, int K, int splitOut)
{
    extern __shared__ uint32_t sm2[];
    uint32_t* sAh = sm2;
    uint32_t* sAl = sm2 + 4608;
    uint32_t* sBh = sm2 + 9216;
    uint32_t* sBl = sm2 + 13824;

    const int tid  = threadIdx.x;
    const int lane = tid & 31;
    const int w    = tid >> 5;
    const int m0   = blockIdx.y * 128;
    const int n0   = blockIdx.x * 128;
    const int mb   = (w & 1) * 64;
    const int nb   = (w >> 1) * 32;
    const int g    = lane >> 2;
    const int q    = lane & 3;
    const int Kw   = K >> 1;           // words per row

    float acc[4][4][4];
#pragma unroll
    for (int mt = 0; mt < 4; mt++)
#pragma unroll
        for (int nt = 0; nt < 4; nt++)
#pragma unroll
            for (int i = 0; i < 4; i++) acc[mt][nt][i] = 0.0f;

    const int ldrow = tid >> 3;        // 0..31
    const int ldj   = (tid & 7) * 4;   // word offset in 32-word row

    const int nchunks = K >> 6;
    for (int c = 0; c < nchunks; c++) {
        if (c) __syncthreads();
        const int kw0 = c * 32;
#pragma unroll
        for (int p = 0; p < 4; p++) {
            int r = ldrow + 32 * p;
            uint4 va = *(const uint4*)(Ah  + (size_t)(m0 + r) * Kw + kw0 + ldj);
            uint4 vb = *(const uint4*)(Al  + (size_t)(m0 + r) * Kw + kw0 + ldj);
            uint4 vc = *(const uint4*)(Bth + (size_t)(n0 + r) * Kw + kw0 + ldj);
            uint4 vd = *(const uint4*)(Btl + (size_t)(n0 + r) * Kw + kw0 + ldj);
            *(uint4*)&sAh[r * SP2 + ldj] = va;
            *(uint4*)&sAl[r * SP2 + ldj] = vb;
            *(uint4*)&sBh[r * SP2 + ldj] = vc;
            *(uint4*)&sBl[r * SP2 + ldj] = vd;
        }
        __syncthreads();

#pragma unroll
        for (int ks = 0; ks < 4; ks++) {
            const int kp0 = ks * 8;
#pragma unroll
            for (int combo = 0; combo < 3; combo++) {
                const uint32_t* As = (combo == 2) ? sAl : sAh;
                const uint32_t* Bs = (combo == 1) ? sBl : sBh;
                uint32_t a[4][4], b[4][2];
#pragma unroll
                for (int mt = 0; mt < 4; mt++) {
                    int base = (mb + mt * 16 + g) * SP2 + kp0 + q;
                    a[mt][0] = As[base];
                    a[mt][1] = As[base + 8 * SP2];
                    a[mt][2] = As[base + 4];
                    a[mt][3] = As[base + 8 * SP2 + 4];
                }
#pragma unroll
                for (int nt = 0; nt < 4; nt++) {
                    int base = (nb + nt * 8 + g) * SP2 + kp0 + q;
                    b[nt][0] = Bs[base];
                    b[nt][1] = Bs[base + 4];
                }
#pragma unroll
                for (int mt = 0; mt < 4; mt++)
#pragma unroll
                    for (int nt = 0; nt < 4; nt++)
                        MMA_BF16(acc[mt][nt], a[mt], b[nt]);
            }
        }
    }

    // epilogue
    const int Nw = N >> 1;
#pragma unroll
    for (int mt = 0; mt < 4; mt++) {
        int row = m0 + mb + mt * 16 + g;
#pragma unroll
        for (int nt = 0; nt < 4; nt++) {
            int col = n0 + nb + nt * 8 + 2 * q;
            float2 bv = *(const float2*)&bias[col];
            float c0 = acc[mt][nt][0] + bv.x, c1 = acc[mt][nt][1] + bv.y;
            float c2 = acc[mt][nt][2] + bv.x, c3 = acc[mt][nt][3] + bv.y;
            if (splitOut) {
                size_t w0 = (size_t)row * Nw + (col >> 1);
                size_t w1 = (size_t)(row + 8) * Nw + (col >> 1);
                uint32_t h0 = bf16_rne_bits(c0), h1 = bf16_rne_bits(c1);
                uint32_t h2 = bf16_rne_bits(c2), h3 = bf16_rne_bits(c3);
                Ch[w0] = (h0 >> 16) | (h1 & 0xFFFF0000u);
                Cl[w0] = bf16pack(c0 - ASF(h0), c1 - ASF(h1));
                Ch[w1] = (h2 >> 16) | (h3 & 0xFFFF0000u);
                Cl[w1] = bf16pack(c2 - ASF(h2), c3 - ASF(h3));
            } else {
                *(float2*)&Cf[(size_t)row * N + col]       = make_float2(c0, c1);
                *(float2*)&Cf[(size_t)(row + 8) * N + col] = make_float2(c2, c3);
            }
        }
    }
}

// ---------------------------------------------------------------------------
// MMA flash-attention (causal). grid (Tq/128, B*NH), 256 threads / 8 warps.
// Q-tile 128 rows (16/warp, frags in regs), K/V tiles 64 keys.
// bf16 hi/lo split for QK^T and PV (3 products each), fp32 softmax.
// ---------------------------------------------------------------------------
// smem (words): Q staging hi[0..4607] lo[4608..9215]; then reused:
//   Ks_hi 0, Ks_lo 2304, Vt_hi 4608, Vt_lo 6912  (Ks [key][dpair]x36, Vt [d][kpair]x36)
__global__ __launch_bounds__(256, 2)
void attn_mma_kernel(const __nv_bfloat16* __restrict__ qkvh_,
                     const __nv_bfloat16* __restrict__ qkvl_,
                     __nv_bfloat16* __restrict__ yh_,
                     __nv_bfloat16* __restrict__ yl_)
{
    __shared__ uint32_t sm_[9216];

    const uint32_t* qh32 = (const uint32_t*)qkvh_;
    const uint32_t* ql32 = (const uint32_t*)qkvl_;
    uint32_t* yh32 = (uint32_t*)yh_;
    uint32_t* yl32 = (uint32_t*)yl_;

    const int tid  = threadIdx.x;
    const int lane = tid & 31;
    const int w    = tid >> 5;            // 0..7
    const int g    = lane >> 2;
    const int q    = lane & 3;
    const int bh   = blockIdx.y;
    const int b    = bh >> 4;
    const int h    = bh & 15;
    const int qt   = blockIdx.x;
    const int q0   = qt * 128;
    const float scale = 0.125f;           // 1/sqrt(64)

    const size_t base = (size_t)(b * Tq) * 1536;   // word base of qkv for batch b

    // ---- stage Q (hi+lo) then build register fragments ----
    {
        int row = tid >> 3;
        int j4  = (tid & 7) * 4;
#pragma unroll
        for (int p = 0; p < 4; p++) {
            int r = row + 32 * p;
            size_t gw = base + (size_t)(q0 + r) * 1536 + h * 32 + j4;
            *(uint4*)&sm_[r * 36 + j4]        = *(const uint4*)(qh32 + gw);
            *(uint4*)&sm_[4608 + r * 36 + j4] = *(const uint4*)(ql32 + gw);
        }
    }
    __syncthreads();
    uint32_t qa_h[4][4], qa_l[4][4];
    {
        int r0 = 16 * w + g;
#pragma unroll
        for (int ks = 0; ks < 4; ks++) {
            int ba = r0 * 36 + 8 * ks + q;
            qa_h[ks][0] = sm_[ba];
            qa_h[ks][1] = sm_[ba + 8 * 36];
            qa_h[ks][2] = sm_[ba + 4];
            qa_h[ks][3] = sm_[ba + 8 * 36 + 4];
            qa_l[ks][0] = sm_[4608 + ba];
            qa_l[ks][1] = sm_[4608 + ba + 8 * 36];
            qa_l[ks][2] = sm_[4608 + ba + 4];
            qa_l[ks][3] = sm_[4608 + ba + 8 * 36 + 4];
        }
    }

    float mrow[2] = {-1e30f, -1e30f};
    float lrow[2] = {0.0f, 0.0f};
    float acc[8][4];
#pragma unroll
    for (int nt = 0; nt < 8; nt++)
#pragma unroll
        for (int i = 0; i < 4; i++) acc[nt][i] = 0.0f;

    const int ktmax = 2 * (qt + 1);
    for (int kt = 0; kt < ktmax; kt++) {
        __syncthreads();    // prior compute done (covers Q-frag extraction on kt=0)

        // ---- load K tile (64 keys x 64 d) hi/lo into Ks [key][dpair] ----
        {
            int row = tid >> 3;
            int j4  = (tid & 7) * 4;
#pragma unroll
            for (int p = 0; p < 2; p++) {
                int r = row + 32 * p;
                size_t gw = base + (size_t)(64 * kt + r) * 1536 + 512 + h * 32 + j4;
                *(uint4*)&sm_[r * 36 + j4]        = *(const uint4*)(qh32 + gw);
                *(uint4*)&sm_[2304 + r * 36 + j4] = *(const uint4*)(ql32 + gw);
            }
        }
        // ---- load V tile + transpose-repack into Vt [d][kpair] ----
        {
            int kp = tid & 31;
            int dg = tid >> 5;
            size_t gv = base + (size_t)(64 * kt + 2 * kp) * 1536 + 1024 + h * 32 + dg * 4;
            uint4 a0 = *(const uint4*)(qh32 + gv);
            uint4 a1 = *(const uint4*)(qh32 + gv + 1536);
            uint4 b0 = *(const uint4*)(ql32 + gv);
            uint4 b1 = *(const uint4*)(ql32 + gv + 1536);
            const uint32_t* a0w = (const uint32_t*)&a0;
            const uint32_t* a1w = (const uint32_t*)&a1;
            const uint32_t* b0w = (const uint32_t*)&b0;
            const uint32_t* b1w = (const uint32_t*)&b1;
#pragma unroll
            for (int j = 0; j < 4; j++) {
                int d = 8 * dg + 2 * j;
                sm_[4608 + d * 36 + kp]       = __byte_perm(a0w[j], a1w[j], 0x5410);
                sm_[4608 + (d + 1) * 36 + kp] = __byte_perm(a0w[j], a1w[j], 0x7632);
                sm_[6912 + d * 36 + kp]       = __byte_perm(b0w[j], b1w[j], 0x5410);
                sm_[6912 + (d + 1) * 36 + kp] = __byte_perm(b0w[j], b1w[j], 0x7632);
            }
        }
        __syncthreads();

        // warp-uniform skip: whole warp-tile above diagonal
        if (64 * kt > q0 + 16 * w + 15) continue;

        // ---- S = Q K^T (m16 x n64), 3-product split ----
        float s[8][4];
#pragma unroll
        for (int nt = 0; nt < 8; nt++)
#pragma unroll
            for (int i = 0; i < 4; i++) s[nt][i] = 0.0f;

#pragma unroll
        for (int ks = 0; ks < 4; ks++) {
#pragma unroll
            for (int nt = 0; nt < 8; nt++) {
                int ba = (8 * nt + g) * 36 + 8 * ks + q;
                uint32_t kb_h[2] = { sm_[ba],        sm_[ba + 4] };
                uint32_t kb_l[2] = { sm_[2304 + ba], sm_[2304 + ba + 4] };
                MMA_BF16(s[nt], qa_h[ks], kb_h);
                MMA_BF16(s[nt], qa_h[ks], kb_l);
                MMA_BF16(s[nt], qa_l[ks], kb_h);
            }
        }

        // ---- scale + causal mask ----
        const int rowa = q0 + 16 * w + g;
        const int rowb = rowa + 8;
        const bool domask = (64 * kt + 63 > rowa);   // covers rowb too conservatively
#pragma unroll
        for (int nt = 0; nt < 8; nt++) {
#pragma unroll
            for (int i = 0; i < 4; i++) s[nt][i] *= scale;
            if (domask) {
                int kbase = 64 * kt + 8 * nt + 2 * q;
                if (kbase     > rowa) s[nt][0] = -1e30f;
                if (kbase + 1 > rowa) s[nt][1] = -1e30f;
                if (kbase     > rowb) s[nt][2] = -1e30f;
                if (kbase + 1 > rowb) s[nt][3] = -1e30f;
            }
        }

        // ---- online softmax (rows g and g+8) ----
#pragma unroll
        for (int r = 0; r < 2; r++) {
            float mx = -1e30f;
#pragma unroll
            for (int nt = 0; nt < 8; nt++)
                mx = fmaxf(mx, fmaxf(s[nt][2 * r], s[nt][2 * r + 1]));
            mx = fmaxf(mx, __shfl_xor_sync(0xffffffffu, mx, 1));
            mx = fmaxf(mx, __shfl_xor_sync(0xffffffffu, mx, 2));
            float mnew  = fmaxf(mrow[r], mx);
            float alpha = __expf(mrow[r] - mnew);
            float sum = 0.0f;
#pragma unroll
            for (int nt = 0; nt < 8; nt++) {
                s[nt][2 * r]     = __expf(s[nt][2 * r]     - mnew);
                s[nt][2 * r + 1] = __expf(s[nt][2 * r + 1] - mnew);
                sum += s[nt][2 * r] + s[nt][2 * r + 1];
            }
            sum += __shfl_xor_sync(0xffffffffu, sum, 1);
            sum += __shfl_xor_sync(0xffffffffu, sum, 2);
            lrow[r] = lrow[r] * alpha + sum;
            mrow[r] = mnew;
#pragma unroll
            for (int nt = 0; nt < 8; nt++) {
                acc[nt][2 * r]     *= alpha;
                acc[nt][2 * r + 1] *= alpha;
            }
        }

        // ---- PV: P (from S frags, split) x V (split), accumulate ----
#pragma unroll
        for (int t = 0; t < 4; t++) {
            uint32_t h0 = bf16_rne_bits(s[2 * t][0]),     h1 = bf16_rne_bits(s[2 * t][1]);
            uint32_t h2 = bf16_rne_bits(s[2 * t][2]),     h3 = bf16_rne_bits(s[2 * t][3]);
            uint32_t h4 = bf16_rne_bits(s[2 * t + 1][0]), h5 = bf16_rne_bits(s[2 * t + 1][1]);
            uint32_t h6 = bf16_rne_bits(s[2 * t + 1][2]), h7 = bf16_rne_bits(s[2 * t + 1][3]);
            uint32_t ph[4], pl[4];
            ph[0] = (h0 >> 16) | (h1 & 0xFFFF0000u);
            ph[1] = (h2 >> 16) | (h3 & 0xFFFF0000u);
            ph[2] = (h4 >> 16) | (h5 & 0xFFFF0000u);
            ph[3] = (h6 >> 16) | (h7 & 0xFFFF0000u);
            pl[0] = bf16pack(s[2 * t][0]     - ASF(h0), s[2 * t][1]     - ASF(h1));
            pl[1] = bf16pack(s[2 * t][2]     - ASF(h2), s[2 * t][3]     - ASF(h3));
            pl[2] = bf16pack(s[2 * t + 1][0] - ASF(h4), s[2 * t + 1][1] - ASF(h5));
            pl[3] = bf16pack(s[2 * t + 1][2] - ASF(h6), s[2 * t + 1][3] - ASF(h7));
#pragma unroll
            for (int nt = 0; nt < 8; nt++) {
                int ba = (8 * nt + g) * 36 + 8 * t + q;
                uint32_t vb_h[2] = { sm_[4608 + ba], sm_[4608 + ba + 4] };
                uint32_t vb_l[2] = { sm_[6912 + ba], sm_[6912 + ba + 4] };
                MMA_BF16(acc[nt], ph, vb_h);
                MMA_BF16(acc[nt], pl, vb_h);
                MMA_BF16(acc[nt], ph, vb_l);
            }
        }
    }

    // ---- epilogue: normalize, split-store y ----
    {
        float inv0 = 1.0f / lrow[0];
        float inv1 = 1.0f / lrow[1];
        int r = q0 + 16 * w + g;
        size_t w0b = ((size_t)(b * Tq) + r) * 512 + h * 32 + q;
        size_t w1b = w0b + (size_t)8 * 512;
#pragma unroll
        for (int nt = 0; nt < 8; nt++) {
            float v0 = acc[nt][0] * inv0, v1 = acc[nt][1] * inv0;
            float v2 = acc[nt][2] * inv1, v3 = acc[nt][3] * inv1;
            uint32_t h0 = bf16_rne_bits(v0), h1 = bf16_rne_bits(v1);
            uint32_t h2 = bf16_rne_bits(v2), h3 = bf16_rne_bits(v3);
            yh32[w0b + 4 * nt] = (h0 >> 16) | (h1 & 0xFFFF0000u);
            yl32[w0b + 4 * nt] = bf16pack(v0 - ASF(h0), v1 - ASF(h1));
            yh32[w1b + 4 * nt] = (h2 >> 16) | (h3 & 0xFFFF0000u);
            yl32[w1b + 4 * nt] = bf16pack(v2 - ASF(h2), v3 - ASF(h3));
        }
    }
}

// ---------------------------------------------------------------------------
// Launch
// ---------------------------------------------------------------------------
extern "C" void kernel_launch(void* const* d_in, const int* in_sizes, int n_in,
                              void* d_out, int out_size)
{
    (void)in_sizes; (void)n_in; (void)out_size;
    const float* x      = (const float*)d_in[0];
    const float* W_attn = (const float*)d_in[1];
    const float* b_attn = (const float*)d_in[2];
    const float* W_proj = (const float*)d_in[3];
    const float* b_proj = (const float*)d_in[4];
    float* out = (float*)d_out;

    __nv_bfloat16 *xh, *xl, *wqh, *wql, *wph, *wpl, *qh, *ql, *yh, *yl;
    cudaGetSymbolAddress((void**)&xh,  g_xh);
    cudaGetSymbolAddress((void**)&xl,  g_xl);
    cudaGetSymbolAddress((void**)&wqh, g_wqkvT_h);
    cudaGetSymbolAddress((void**)&wql, g_wqkvT_l);
    cudaGetSymbolAddress((void**)&wph, g_wprojT_h);
    cudaGetSymbolAddress((void**)&wpl, g_wprojT_l);
    cudaGetSymbolAddress((void**)&qh,  g_qkvh);
    cudaGetSymbolAddress((void**)&ql,  g_qkvl);
    cudaGetSymbolAddress((void**)&yh,  g_yh);
    cudaGetSymbolAddress((void**)&yl,  g_yl);

    cudaFuncSetAttribute(gemm_mma2_kernel,
                         cudaFuncAttributeMaxDynamicSharedMemorySize, G2_BYTES);

    // 0) pre-split operands
    cvt_split_kernel<<<(MQ * Cq / 4 + 255) / 256, 256>>>(x, xh, xl, MQ * Cq / 4);
    cvt_splitT_kernel<<<dim3(C3 / 32, Cq / 32), 256>>>(W_attn, wqh, wql, Cq, C3);
    cvt_splitT_kernel<<<dim3(Cq / 32, Cq / 32), 256>>>(W_proj, wph, wpl, Cq, Cq);

    // 1) qkv(hi/lo) = x @ W_attn + b_attn
    gemm_mma2_kernel<<<dim3(C3 / 128, MQ / 128), 256, G2_BYTES>>>(
        (const uint32_t*)xh, (const uint32_t*)xl,
        (const uint32_t*)wqh, (const uint32_t*)wql,
        b_attn, nullptr, (uint32_t*)qh, (uint32_t*)ql, MQ, C3, Cq, 1);

    // 2) y(hi/lo) = causal_attention(qkv)
    attn_mma_kernel<<<dim3(Tq / 128, Bq * NH), 256>>>(qh, ql, yh, yl);

    // 3) out = y @ W_proj + b_proj  (fp32)
    gemm_mma2_kernel<<<dim3(Cq / 128, MQ / 128), 256, G2_BYTES>>>(
        (const uint32_t*)yh, (const uint32_t*)yl,
        (const uint32_t*)wph, (const uint32_t*)wpl,
        b_proj, out, nullptr, nullptr, MQ, Cq, Cq, 0);
}

// round 10
// speedup vs baseline: 2.8124x; 1.0403x over previous
#include <cuda_runtime.h>
#include <cuda_bf16.h>
#include <cuda_fp16.h>
#include <math.h>
#include <stdint.h>

// Problem constants
#define Bq   4
#define Tq   2048
#define Cq   1024
#define NH   16
#define HD   64
#define C3   (3 * Cq)          // 3072
#define MQ   (Bq * Tq)         // 8192 rows

// ---------------------------------------------------------------------------
// Scratch (device globals; no runtime allocation allowed)
// ---------------------------------------------------------------------------
__device__ __align__(128) __nv_bfloat16 g_xh[(size_t)MQ * Cq];
__device__ __align__(128) __nv_bfloat16 g_xl[(size_t)MQ * Cq];
__device__ __align__(128) __nv_bfloat16 g_wqkvT_h[(size_t)C3 * Cq];
__device__ __align__(128) __nv_bfloat16 g_wqkvT_l[(size_t)C3 * Cq];
__device__ __align__(128) __nv_bfloat16 g_wprojT_h[(size_t)Cq * Cq];
__device__ __align__(128) __nv_bfloat16 g_wprojT_l[(size_t)Cq * Cq];
__device__ __align__(128) __half       g_qkvh[(size_t)MQ * C3];   // fp16 hi
__device__ __align__(128) __half       g_qkvl[(size_t)MQ * C3];   // fp16 lo
__device__ __align__(128) __nv_bfloat16 g_yh[(size_t)MQ * Cq];
__device__ __align__(128) __nv_bfloat16 g_yl[(size_t)MQ * Cq];

// ---------------------------------------------------------------------------
// helpers
// ---------------------------------------------------------------------------
__device__ __forceinline__ uint32_t smem_u32(const void* p) {
    uint32_t a;
    asm("{ .reg .u64 t; cvta.to.shared.u64 t, %1; cvt.u32.u64 %0, t; }"
        : "=r"(a) : "l"(p));
    return a;
}
__device__ __forceinline__ uint32_t bf16_rne_bits(float x) {
    uint32_t u = __float_as_uint(x);
    return (u + 0x7FFFu + ((u >> 16) & 1u)) & 0xFFFF0000u;
}
__device__ __forceinline__ uint32_t bf16pack(float lo_elem, float hi_elem) {
    uint32_t r;
    asm("cvt.rn.bf16x2.f32 %0, %1, %2;" : "=r"(r) : "f"(hi_elem), "f"(lo_elem));
    return r;
}
#define ASF(u) __uint_as_float(u)

#define MMA_BF16(d, av, bv)                                                    \
  asm volatile("mma.sync.aligned.m16n8k16.row.col.f32.bf16.bf16.f32 "          \
      "{%0,%1,%2,%3}, {%4,%5,%6,%7}, {%8,%9}, {%0,%1,%2,%3};"                  \
      : "+f"((d)[0]), "+f"((d)[1]), "+f"((d)[2]), "+f"((d)[3])                 \
      : "r"((av)[0]), "r"((av)[1]), "r"((av)[2]), "r"((av)[3]),                \
        "r"((bv)[0]), "r"((bv)[1]))

#define MMA_F16(d, av, bv)                                                     \
  asm volatile("mma.sync.aligned.m16n8k16.row.col.f32.f16.f16.f32 "            \
      "{%0,%1,%2,%3}, {%4,%5,%6,%7}, {%8,%9}, {%0,%1,%2,%3};"                  \
      : "+f"((d)[0]), "+f"((d)[1]), "+f"((d)[2]), "+f"((d)[3])                 \
      : "r"((av)[0]), "r"((av)[1]), "r"((av)[2]), "r"((av)[3]),                \
        "r"((bv)[0]), "r"((bv)[1]))

#define LDSM4(R0, R1, R2, R3, A)                                               \
  asm volatile("ldmatrix.sync.aligned.m8n8.x4.shared.b16 {%0,%1,%2,%3}, [%4];" \
      : "=r"(R0), "=r"(R1), "=r"(R2), "=r"(R3) : "r"(A))

#define CPA16(dst, src)                                                        \
  asm volatile("cp.async.cg.shared.global [%0], [%1], 16;"                     \
      :: "r"(dst), "l"(src) : "memory")
#define CPA_COMMIT() asm volatile("cp.async.commit_group;" ::: "memory")
#define CPA_WAIT1()  asm volatile("cp.async.wait_group 1;" ::: "memory")
#define CPA_WAIT0()  asm volatile("cp.async.wait_group 0;" ::: "memory")

// ---------------------------------------------------------------------------
// cvt kernels: fp32 -> bf16 hi/lo
// ---------------------------------------------------------------------------
__global__ void cvt_split_kernel(const float* __restrict__ a,
                                 __nv_bfloat16* __restrict__ hi,
                                 __nv_bfloat16* __restrict__ lo, int n4)
{
    int i = blockIdx.x * 256 + threadIdx.x;
    if (i >= n4) return;
    float4 v = ((const float4*)a)[i];
    uint32_t hx = bf16_rne_bits(v.x), hy = bf16_rne_bits(v.y);
    uint32_t hz = bf16_rne_bits(v.z), hw = bf16_rne_bits(v.w);
    uint32_t* h32 = (uint32_t*)hi;
    uint32_t* l32 = (uint32_t*)lo;
    h32[2 * i + 0] = (hx >> 16) | (hy & 0xFFFF0000u);
    h32[2 * i + 1] = (hz >> 16) | (hw & 0xFFFF0000u);
    l32[2 * i + 0] = bf16pack(v.x - ASF(hx), v.y - ASF(hy));
    l32[2 * i + 1] = bf16pack(v.z - ASF(hz), v.w - ASF(hw));
}

// W[K][N] -> out[N][K] hi/lo
__global__ void cvt_splitT_kernel(const float* __restrict__ w,
                                  __nv_bfloat16* __restrict__ th,
                                  __nv_bfloat16* __restrict__ tl, int K, int N)
{
    __shared__ float t[32][33];
    int tx = threadIdx.x & 31, ty = threadIdx.x >> 5;
    int k0 = blockIdx.y * 32, n0 = blockIdx.x * 32;
#pragma unroll
    for (int r = 0; r < 4; r++)
        t[ty + 8 * r][tx] = w[(size_t)(k0 + ty + 8 * r) * N + n0 + tx];
    __syncthreads();
#pragma unroll
    for (int r = 0; r < 4; r++) {
        int n = n0 + ty + 8 * r;
        float v = t[tx][ty + 8 * r];
        uint32_t h = bf16_rne_bits(v);
        th[(size_t)n * K + k0 + tx] = __ushort_as_bfloat16((unsigned short)(h >> 16));
        float rlo = v - ASF(h);
        uint32_t hl = bf16_rne_bits(rlo);
        tl[(size_t)n * K + k0 + tx] = __ushort_as_bfloat16((unsigned short)(hl >> 16));
    }
}

// ---------------------------------------------------------------------------
// Pipelined warp-MMA GEMM: C = (Ah+Al)[M,K] @ (Bth+Btl)^T + bias
// cp.async 2-stage, K-chunk 32, ldmatrix frags, 128x128 CTA / 8 warps.
// outMode 0: fp32 Cf.  outMode 1: fp16 hi/lo (Ch/Cl word arrays).
// ---------------------------------------------------------------------------
#define SP3  20                 // words per smem row (16 data + 4 pad)
#define ARR  2560               // words per array (128*20)
#define STG3 10240              // words per stage (4 arrays)
#define G3_BYTES (2 * STG3 * 4) // 81920

__global__ __launch_bounds__(256, 2)
void gemm_mma3_kernel(const uint32_t* __restrict__ Ah, const uint32_t* __restrict__ Al,
                      const uint32_t* __restrict__ Bth, const uint32_t* __restrict__ Btl,
                      const float* __restrict__ bias, float* __restrict__ Cf,
                      uint32_t* __restrict__ Ch, uint32_t* __restrict__ Cl,
                      int M, int N, int K, int outMode)
{
    extern __shared__ uint32_t sm3[];
    const uint32_t sb = smem_u32(sm3);

    const int tid  = threadIdx.x;
    const int lane = tid & 31;
    const int w    = tid >> 5;
    const int m0   = blockIdx.y * 128;
    const int n0   = blockIdx.x * 128;
    const int mb   = (w & 1) * 64;
    const int nb   = (w >> 1) * 32;
    const int g    = lane >> 2;
    const int q    = lane & 3;
    const int Kw   = K >> 1;

    float acc[4][4][4];
#pragma unroll
    for (int mt = 0; mt < 4; mt++)
#pragma unroll
        for (int nt = 0; nt < 4; nt++)
#pragma unroll
            for (int i = 0; i < 4; i++) acc[mt][nt][i] = 0.0f;

    const int prow = tid >> 2;          // 0..63
    const int pseg = (tid & 3) * 4;     // word offset

    auto do_prefetch = [&](int c, int st) {
        const uint32_t dbase = sb + (uint32_t)st * STG3 * 4;
        const int bk = c * 16;
#pragma unroll
        for (int pp = 0; pp < 2; pp++) {
            int row = prow + pp * 64;
            size_t soA = (size_t)(m0 + row) * Kw + bk + pseg;
            size_t soB = (size_t)(n0 + row) * Kw + bk + pseg;
            uint32_t d = dbase + (uint32_t)(row * SP3 + pseg) * 4;
            CPA16(d,               Ah  + soA);
            CPA16(d + ARR * 4,     Al  + soA);
            CPA16(d + 2 * ARR * 4, Bth + soB);
            CPA16(d + 3 * ARR * 4, Btl + soB);
        }
        CPA_COMMIT();
    };

    // lane-invariant ldmatrix address components
    const uint32_t a_rw = (uint32_t)((mb + (lane & 15)) * SP3 + ((lane >> 4) << 2));
    const uint32_t b_rw = (uint32_t)((nb + (lane & 7) + ((lane >> 4) << 3)) * SP3
                                     + (((lane >> 3) & 1) << 2));

    const int nch = K >> 5;
    do_prefetch(0, 0);
    for (int c = 0; c < nch; c++) {
        if (c + 1 < nch) { do_prefetch(c + 1, (c + 1) & 1); CPA_WAIT1(); }
        else             { CPA_WAIT0(); }
        __syncthreads();

        const uint32_t ab = sb + (uint32_t)(c & 1) * STG3 * 4;
#pragma unroll
        for (int ks = 0; ks < 2; ks++) {
            const uint32_t aH = ab + (a_rw + ks * 8) * 4;
            const uint32_t bH = ab + (2 * ARR + b_rw + ks * 8) * 4;
            uint32_t a_hi[4][4], a_lo[4][4], b_hi[4][2], b_lo[4][2];
#pragma unroll
            for (int mt = 0; mt < 4; mt++)
                LDSM4(a_hi[mt][0], a_hi[mt][1], a_hi[mt][2], a_hi[mt][3],
                      aH + mt * 16 * SP3 * 4);
#pragma unroll
            for (int np = 0; np < 2; np++)
                LDSM4(b_hi[2 * np][0], b_hi[2 * np][1],
                      b_hi[2 * np + 1][0], b_hi[2 * np + 1][1],
                      bH + np * 16 * SP3 * 4);
            // hi * hi
#pragma unroll
            for (int mt = 0; mt < 4; mt++)
#pragma unroll
                for (int nt = 0; nt < 4; nt++)
                    MMA_BF16(acc[mt][nt], a_hi[mt], b_hi[nt]);
            // lo * hi
#pragma unroll
            for (int mt = 0; mt < 4; mt++)
                LDSM4(a_lo[mt][0], a_lo[mt][1], a_lo[mt][2], a_lo[mt][3],
                      aH + (ARR + mt * 16 * SP3) * 4);
#pragma unroll
            for (int mt = 0; mt < 4; mt++)
#pragma unroll
                for (int nt = 0; nt < 4; nt++)
                    MMA_BF16(acc[mt][nt], a_lo[mt], b_hi[nt]);
            // hi * lo
#pragma unroll
            for (int np = 0; np < 2; np++)
                LDSM4(b_lo[2 * np][0], b_lo[2 * np][1],
                      b_lo[2 * np + 1][0], b_lo[2 * np + 1][1],
                      bH + (ARR + np * 16 * SP3) * 4);
#pragma unroll
            for (int mt = 0; mt < 4; mt++)
#pragma unroll
                for (int nt = 0; nt < 4; nt++)
                    MMA_BF16(acc[mt][nt], a_hi[mt], b_lo[nt]);
        }
        __syncthreads();
    }

    // ---- epilogue ----
    const int Nw = N >> 1;
#pragma unroll
    for (int mt = 0; mt < 4; mt++) {
        int row = m0 + mb + mt * 16 + g;
#pragma unroll
        for (int nt = 0; nt < 4; nt++) {
            int col = n0 + nb + nt * 8 + 2 * q;
            float2 bv = *(const float2*)&bias[col];
            float c0 = acc[mt][nt][0] + bv.x, c1 = acc[mt][nt][1] + bv.y;
            float c2 = acc[mt][nt][2] + bv.x, c3 = acc[mt][nt][3] + bv.y;
            if (outMode) {
                size_t w0 = (size_t)row * Nw + (col >> 1);
                size_t w1 = (size_t)(row + 8) * Nw + (col >> 1);
                uint32_t hA, hB, lA, lB;
                asm("cvt.rn.f16x2.f32 %0, %1, %2;" : "=r"(hA) : "f"(c1), "f"(c0));
                asm("cvt.rn.f16x2.f32 %0, %1, %2;" : "=r"(hB) : "f"(c3), "f"(c2));
                __half2 ha = *(__half2*)&hA;
                __half2 hb = *(__half2*)&hB;
                float r0 = c0 - __low2float(ha), r1 = c1 - __high2float(ha);
                float r2 = c2 - __low2float(hb), r3 = c3 - __high2float(hb);
                asm("cvt.rn.f16x2.f32 %0, %1, %2;" : "=r"(lA) : "f"(r1), "f"(r0));
                asm("cvt.rn.f16x2.f32 %0, %1, %2;" : "=r"(lB) : "f"(r3), "f"(r2));
                Ch[w0] = hA; Cl[w0] = lA;
                Ch[w1] = hB; Cl[w1] = lB;
            } else {
                *(float2*)&Cf[(size_t)row * N + col]       = make_float2(c0, c1);
                *(float2*)&Cf[(size_t)(row + 8) * N + col] = make_float2(c2, c3);
            }
        }
    }
}

// ---------------------------------------------------------------------------
// MMA flash-attention (causal), fp16 operands.
// QK^T: 3-product fp16 hi/lo split (keeps S accurate for exp).
// PV:   P as single fp16 x V(hi,lo) -> 2 products.
// grid (Tq/128, B*NH), 256 threads / 8 warps.
// ---------------------------------------------------------------------------
__global__ __launch_bounds__(256, 2)
void attn_mma_kernel(const __half* __restrict__ qkvh_,
                     const __half* __restrict__ qkvl_,
                     __nv_bfloat16* __restrict__ yh_,
                     __nv_bfloat16* __restrict__ yl_)
{
    __shared__ uint32_t sm_[9216];

    const uint32_t* qh32 = (const uint32_t*)qkvh_;
    const uint32_t* ql32 = (const uint32_t*)qkvl_;
    uint32_t* yh32 = (uint32_t*)yh_;
    uint32_t* yl32 = (uint32_t*)yl_;

    const int tid  = threadIdx.x;
    const int lane = tid & 31;
    const int w    = tid >> 5;
    const int g    = lane >> 2;
    const int q    = lane & 3;
    const int bh   = blockIdx.y;
    const int b    = bh >> 4;
    const int h    = bh & 15;
    const int qt   = blockIdx.x;
    const int q0   = qt * 128;
    const float scale = 0.125f;

    const size_t base = (size_t)(b * Tq) * 1536;

    // ---- stage Q (hi+lo), build register fragments ----
    {
        int row = tid >> 3;
        int j4  = (tid & 7) * 4;
#pragma unroll
        for (int p = 0; p < 4; p++) {
            int r = row + 32 * p;
            size_t gw = base + (size_t)(q0 + r) * 1536 + h * 32 + j4;
            *(uint4*)&sm_[r * 36 + j4]        = *(const uint4*)(qh32 + gw);
            *(uint4*)&sm_[4608 + r * 36 + j4] = *(const uint4*)(ql32 + gw);
        }
    }
    __syncthreads();
    uint32_t qa_h[4][4], qa_l[4][4];
    {
        int r0 = 16 * w + g;
#pragma unroll
        for (int ks = 0; ks < 4; ks++) {
            int ba = r0 * 36 + 8 * ks + q;
            qa_h[ks][0] = sm_[ba];
            qa_h[ks][1] = sm_[ba + 8 * 36];
            qa_h[ks][2] = sm_[ba + 4];
            qa_h[ks][3] = sm_[ba + 8 * 36 + 4];
            qa_l[ks][0] = sm_[4608 + ba];
            qa_l[ks][1] = sm_[4608 + ba + 8 * 36];
            qa_l[ks][2] = sm_[4608 + ba + 4];
            qa_l[ks][3] = sm_[4608 + ba + 8 * 36 + 4];
        }
    }

    float mrow[2] = {-1e30f, -1e30f};
    float lrow[2] = {0.0f, 0.0f};
    float acc[8][4];
#pragma unroll
    for (int nt = 0; nt < 8; nt++)
#pragma unroll
        for (int i = 0; i < 4; i++) acc[nt][i] = 0.0f;

    const int ktmax = 2 * (qt + 1);
    for (int kt = 0; kt < ktmax; kt++) {
        __syncthreads();

        // ---- load K tile hi/lo into [key][dpair] ----
        {
            int row = tid >> 3;
            int j4  = (tid & 7) * 4;
#pragma unroll
            for (int p = 0; p < 2; p++) {
                int r = row + 32 * p;
                size_t gw = base + (size_t)(64 * kt + r) * 1536 + 512 + h * 32 + j4;
                *(uint4*)&sm_[r * 36 + j4]        = *(const uint4*)(qh32 + gw);
                *(uint4*)&sm_[2304 + r * 36 + j4] = *(const uint4*)(ql32 + gw);
            }
        }
        // ---- load V tile + transpose-repack into [d][kpair] ----
        {
            int kp = tid & 31;
            int dg = tid >> 5;
            size_t gv = base + (size_t)(64 * kt + 2 * kp) * 1536 + 1024 + h * 32 + dg * 4;
            uint4 a0 = *(const uint4*)(qh32 + gv);
            uint4 a1 = *(const uint4*)(qh32 + gv + 1536);
            uint4 b0 = *(const uint4*)(ql32 + gv);
            uint4 b1 = *(const uint4*)(ql32 + gv + 1536);
            const uint32_t* a0w = (const uint32_t*)&a0;
            const uint32_t* a1w = (const uint32_t*)&a1;
            const uint32_t* b0w = (const uint32_t*)&b0;
            const uint32_t* b1w = (const uint32_t*)&b1;
#pragma unroll
            for (int j = 0; j < 4; j++) {
                int d = 8 * dg + 2 * j;
                sm_[4608 + d * 36 + kp]       = __byte_perm(a0w[j], a1w[j], 0x5410);
                sm_[4608 + (d + 1) * 36 + kp] = __byte_perm(a0w[j], a1w[j], 0x7632);
                sm_[6912 + d * 36 + kp]       = __byte_perm(b0w[j], b1w[j], 0x5410);
                sm_[6912 + (d + 1) * 36 + kp] = __byte_perm(b0w[j], b1w[j], 0x7632);
            }
        }
        __syncthreads();

        if (64 * kt > q0 + 16 * w + 15) continue;   // warp tile fully masked

        // ---- S = Q K^T, 3-product fp16 split ----
        float s[8][4];
#pragma unroll
        for (int nt = 0; nt < 8; nt++)
#pragma unroll
            for (int i = 0; i < 4; i++) s[nt][i] = 0.0f;

#pragma unroll
        for (int ks = 0; ks < 4; ks++) {
#pragma unroll
            for (int nt = 0; nt < 8; nt++) {
                int ba = (8 * nt + g) * 36 + 8 * ks + q;
                uint32_t kb_h[2] = { sm_[ba],        sm_[ba + 4] };
                uint32_t kb_l[2] = { sm_[2304 + ba], sm_[2304 + ba + 4] };
                MMA_F16(s[nt], qa_h[ks], kb_h);
                MMA_F16(s[nt], qa_h[ks], kb_l);
                MMA_F16(s[nt], qa_l[ks], kb_h);
            }
        }

        // ---- scale + causal mask ----
        const int rowa = q0 + 16 * w + g;
        const int rowb = rowa + 8;
        const bool domask = (64 * kt + 63 > rowa);
#pragma unroll
        for (int nt = 0; nt < 8; nt++) {
#pragma unroll
            for (int i = 0; i < 4; i++) s[nt][i] *= scale;
            if (domask) {
                int kbase = 64 * kt + 8 * nt + 2 * q;
                if (kbase     > rowa) s[nt][0] = -1e30f;
                if (kbase + 1 > rowa) s[nt][1] = -1e30f;
                if (kbase     > rowb) s[nt][2] = -1e30f;
                if (kbase + 1 > rowb) s[nt][3] = -1e30f;
            }
        }

        // ---- online softmax ----
#pragma unroll
        for (int r = 0; r < 2; r++) {
            float mx = -1e30f;
#pragma unroll
            for (int nt = 0; nt < 8; nt++)
                mx = fmaxf(mx, fmaxf(s[nt][2 * r], s[nt][2 * r + 1]));
            mx = fmaxf(mx, __shfl_xor_sync(0xffffffffu, mx, 1));
            mx = fmaxf(mx, __shfl_xor_sync(0xffffffffu, mx, 2));
            float mnew  = fmaxf(mrow[r], mx);
            float alpha = __expf(mrow[r] - mnew);
            float sum = 0.0f;
#pragma unroll
            for (int nt = 0; nt < 8; nt++) {
                s[nt][2 * r]     = __expf(s[nt][2 * r]     - mnew);
                s[nt][2 * r + 1] = __expf(s[nt][2 * r + 1] - mnew);
                sum += s[nt][2 * r] + s[nt][2 * r + 1];
            }
            sum += __shfl_xor_sync(0xffffffffu, sum, 1);
            sum += __shfl_xor_sync(0xffffffffu, sum, 2);
            lrow[r] = lrow[r] * alpha + sum;
            mrow[r] = mnew;
#pragma unroll
            for (int nt = 0; nt < 8; nt++) {
                acc[nt][2 * r]     *= alpha;
                acc[nt][2 * r + 1] *= alpha;
            }
        }

        // ---- PV: single-fp16 P x V(hi,lo) ----
#pragma unroll
        for (int t = 0; t < 4; t++) {
            uint32_t ph[4];
            asm("cvt.rn.f16x2.f32 %0, %1, %2;" : "=r"(ph[0]) : "f"(s[2*t][1]),   "f"(s[2*t][0]));
            asm("cvt.rn.f16x2.f32 %0, %1, %2;" : "=r"(ph[1]) : "f"(s[2*t][3]),   "f"(s[2*t][2]));
            asm("cvt.rn.f16x2.f32 %0, %1, %2;" : "=r"(ph[2]) : "f"(s[2*t+1][1]), "f"(s[2*t+1][0]));
            asm("cvt.rn.f16x2.f32 %0, %1, %2;" : "=r"(ph[3]) : "f"(s[2*t+1][3]), "f"(s[2*t+1][2]));
#pragma unroll
            for (int nt = 0; nt < 8; nt++) {
                int ba = (8 * nt + g) * 36 + 8 * t + q;
                uint32_t vb_h[2] = { sm_[4608 + ba], sm_[4608 + ba + 4] };
                uint32_t vb_l[2] = { sm_[6912 + ba], sm_[6912 + ba + 4] };
                MMA_F16(acc[nt], ph, vb_h);
                MMA_F16(acc[nt], ph, vb_l);
            }
        }
    }

    // ---- epilogue: normalize, bf16-split store of y ----
    {
        float inv0 = 1.0f / lrow[0];
        float inv1 = 1.0f / lrow[1];
        int r = q0 + 16 * w + g;
        size_t w0b = ((size_t)(b * Tq) + r) * 512 + h * 32 + q;
        size_t w1b = w0b + (size_t)8 * 512;
#pragma unroll
        for (int nt = 0; nt < 8; nt++) {
            float v0 = acc[nt][0] * inv0, v1 = acc[nt][1] * inv0;
            float v2 = acc[nt][2] * inv1, v3 = acc[nt][3] * inv1;
            uint32_t h0 = bf16_rne_bits(v0), h1 = bf16_rne_bits(v1);
            uint32_t h2 = bf16_rne_bits(v2), h3 = bf16_rne_bits(v3);
            yh32[w0b + 4 * nt] = (h0 >> 16) | (h1 & 0xFFFF0000u);
            yl32[w0b + 4 * nt] = bf16pack(v0 - ASF(h0), v1 - ASF(h1));
            yh32[w1b + 4 * nt] = (h2 >> 16) | (h3 & 0xFFFF0000u);
            yl32[w1b + 4 * nt] = bf16pack(v2 - ASF(h2), v3 - ASF(h3));
        }
    }
}

// ---------------------------------------------------------------------------
// Launch
// ---------------------------------------------------------------------------
extern "C" void kernel_launch(void* const* d_in, const int* in_sizes, int n_in,
                              void* d_out, int out_size)
{
    (void)in_sizes; (void)n_in; (void)out_size;
    const float* x      = (const float*)d_in[0];
    const float* W_attn = (const float*)d_in[1];
    const float* b_attn = (const float*)d_in[2];
    const float* W_proj = (const float*)d_in[3];
    const float* b_proj = (const float*)d_in[4];
    float* out = (float*)d_out;

    __nv_bfloat16 *xh, *xl, *wqh, *wql, *wph, *wpl, *yh, *yl;
    __half *qh, *ql;
    cudaGetSymbolAddress((void**)&xh,  g_xh);
    cudaGetSymbolAddress((void**)&xl,  g_xl);
    cudaGetSymbolAddress((void**)&wqh, g_wqkvT_h);
    cudaGetSymbolAddress((void**)&wql, g_wqkvT_l);
    cudaGetSymbolAddress((void**)&wph, g_wprojT_h);
    cudaGetSymbolAddress((void**)&wpl, g_wprojT_l);
    cudaGetSymbolAddress((void**)&qh,  g_qkvh);
    cudaGetSymbolAddress((void**)&ql,  g_qkvl);
    cudaGetSymbolAddress((void**)&yh,  g_yh);
    cudaGetSymbolAddress((void**)&yl,  g_yl);

    cudaFuncSetAttribute(gemm_mma3_kernel,
                         cudaFuncAttributeMaxDynamicSharedMemorySize, G3_BYTES);

    // 0) pre-split operands (bf16 hi/lo)
    cvt_split_kernel<<<(MQ * Cq / 4 + 255) / 256, 256>>>(x, xh, xl, MQ * Cq / 4);
    cvt_splitT_kernel<<<dim3(C3 / 32, Cq / 32), 256>>>(W_attn, wqh, wql, Cq, C3);
    cvt_splitT_kernel<<<dim3(Cq / 32, Cq / 32), 256>>>(W_proj, wph, wpl, Cq, Cq);

    // 1) qkv(fp16 hi/lo) = x @ W_attn + b_attn
    gemm_mma3_kernel<<<dim3(C3 / 128, MQ / 128), 256, G3_BYTES>>>(
        (const uint32_t*)xh, (const uint32_t*)xl,
        (const uint32_t*)wqh, (const uint32_t*)wql,
        b_attn, nullptr, (uint32_t*)qh, (uint32_t*)ql, MQ, C3, Cq, 1);

    // 2) y(bf16 hi/lo) = causal_attention(qkv)
    attn_mma_kernel<<<dim3(Tq / 128, Bq * NH), 256>>>(qh, ql, yh, yl);

    // 3) out(fp32) = y @ W_proj + b_proj
    gemm_mma3_kernel<<<dim3(Cq / 128, MQ / 128), 256, G3_BYTES>>>(
        (const uint32_t*)yh, (const uint32_t*)yl,
        (const uint32_t*)wph, (const uint32_t*)wpl,
        b_proj, out, nullptr, nullptr, MQ, Cq, Cq, 0);
}

// round 11
// speedup vs baseline: 3.7202x; 1.3228x over previous
#include <cuda_runtime.h>
#include <cuda_bf16.h>
#include <cuda_fp16.h>
#include <math.h>
#include <stdint.h>

// Problem constants
#define Bq   4
#define Tq   2048
#define Cq   1024
#define NH   16
#define HD   64
#define C3   (3 * Cq)          // 3072
#define MQ   (Bq * Tq)         // 8192 rows

// ---------------------------------------------------------------------------
// Scratch (device globals; no runtime allocation allowed)
// ---------------------------------------------------------------------------
__device__ __align__(128) __half g_x16 [(size_t)MQ * Cq];    // x, fp16
__device__ __align__(128) __half g_wqh [(size_t)C3 * Cq];    // W_attn^T hi
__device__ __align__(128) __half g_wql [(size_t)C3 * Cq];    // W_attn^T lo
__device__ __align__(128) __half g_wph [(size_t)Cq * Cq];    // W_proj^T hi
__device__ __align__(128) __half g_wpl [(size_t)Cq * Cq];    // W_proj^T lo
__device__ __align__(128) __half g_qkvh[(size_t)MQ * C3];    // qkv hi
__device__ __align__(128) __half g_qkvl[(size_t)MQ * C3];    // qkv lo
__device__ __align__(128) __half g_yh  [(size_t)MQ * Cq];    // attn out, fp16

// ---------------------------------------------------------------------------
// helpers
// ---------------------------------------------------------------------------
__device__ __forceinline__ uint32_t smem_u32(const void* p) {
    uint32_t a;
    asm("{ .reg .u64 t; cvta.to.shared.u64 t, %1; cvt.u32.u64 %0, t; }"
        : "=r"(a) : "l"(p));
    return a;
}

#define MMA_F16(d, av, bv)                                                     \
  asm volatile("mma.sync.aligned.m16n8k16.row.col.f32.f16.f16.f32 "            \
      "{%0,%1,%2,%3}, {%4,%5,%6,%7}, {%8,%9}, {%0,%1,%2,%3};"                  \
      : "+f"((d)[0]), "+f"((d)[1]), "+f"((d)[2]), "+f"((d)[3])                 \
      : "r"((av)[0]), "r"((av)[1]), "r"((av)[2]), "r"((av)[3]),                \
        "r"((bv)[0]), "r"((bv)[1]))

#define LDSM4(R0, R1, R2, R3, A)                                               \
  asm volatile("ldmatrix.sync.aligned.m8n8.x4.shared.b16 {%0,%1,%2,%3}, [%4];" \
      : "=r"(R0), "=r"(R1), "=r"(R2), "=r"(R3) : "r"(A))

#define CPA16(dst, src)                                                        \
  asm volatile("cp.async.cg.shared.global [%0], [%1], 16;"                     \
      :: "r"(dst), "l"(src) : "memory")
#define CPA_COMMIT() asm volatile("cp.async.commit_group;" ::: "memory")
#define CPA_WAIT1()  asm volatile("cp.async.wait_group 1;" ::: "memory")
#define CPA_WAIT0()  asm volatile("cp.async.wait_group 0;" ::: "memory")

#define F16X2(dst, hi_f, lo_f)                                                 \
  asm("cvt.rn.f16x2.f32 %0, %1, %2;" : "=r"(dst) : "f"(hi_f), "f"(lo_f))

// ---------------------------------------------------------------------------
// cvt kernels
// ---------------------------------------------------------------------------
__global__ void cvt_f16_kernel(const float* __restrict__ a,
                               __half* __restrict__ o, int n4)
{
    int i = blockIdx.x * 256 + threadIdx.x;
    if (i >= n4) return;
    float4 v = ((const float4*)a)[i];
    uint32_t w0, w1;
    F16X2(w0, v.y, v.x);
    F16X2(w1, v.w, v.z);
    uint32_t* o32 = (uint32_t*)o;
    o32[2 * i + 0] = w0;
    o32[2 * i + 1] = w1;
}

// W[K][N] -> out[N][K] fp16 hi/lo
__global__ void cvt_splitT_f16_kernel(const float* __restrict__ w,
                                      __half* __restrict__ th,
                                      __half* __restrict__ tl, int K, int N)
{
    __shared__ float t[32][33];
    int tx = threadIdx.x & 31, ty = threadIdx.x >> 5;
    int k0 = blockIdx.y * 32, n0 = blockIdx.x * 32;
#pragma unroll
    for (int r = 0; r < 4; r++)
        t[ty + 8 * r][tx] = w[(size_t)(k0 + ty + 8 * r) * N + n0 + tx];
    __syncthreads();
#pragma unroll
    for (int r = 0; r < 4; r++) {
        int n = n0 + ty + 8 * r;
        float v = t[tx][ty + 8 * r];
        __half hh = __float2half_rn(v);
        th[(size_t)n * K + k0 + tx] = hh;
        tl[(size_t)n * K + k0 + tx] = __float2half_rn(v - __half2float(hh));
    }
}

// ---------------------------------------------------------------------------
// Pipelined warp-MMA GEMM: C = A[M,K] @ (Bth+Btl)^T + bias   (all fp16 in)
// 2-product: acc = a*b_hi + a*b_lo. cp.async 2-stage, K-chunk 32,
// ldmatrix frags, 128x128 CTA / 8 warps.
// outMode 0: fp32 Cf.  outMode 1: fp16 hi/lo (Ch/Cl word arrays).
// ---------------------------------------------------------------------------
#define SP3  20                  // words per smem row (16 data + 4 pad)
#define ARR  2560                // words per array (128*20)
#define STG4 7680                // words per stage (3 arrays)
#define G4_BYTES (2 * STG4 * 4)  // 61440

__global__ __launch_bounds__(256, 2)
void gemm_mma4_kernel(const uint32_t* __restrict__ Ah,
                      const uint32_t* __restrict__ Bth, const uint32_t* __restrict__ Btl,
                      const float* __restrict__ bias, float* __restrict__ Cf,
                      uint32_t* __restrict__ Ch, uint32_t* __restrict__ Cl,
                      int M, int N, int K, int outMode)
{
    extern __shared__ uint32_t sm4[];
    const uint32_t sb = smem_u32(sm4);

    const int tid  = threadIdx.x;
    const int lane = tid & 31;
    const int w    = tid >> 5;
    const int m0   = blockIdx.y * 128;
    const int n0   = blockIdx.x * 128;
    const int mb   = (w & 1) * 64;
    const int nb   = (w >> 1) * 32;
    const int g    = lane >> 2;
    const int q    = lane & 3;
    const int Kw   = K >> 1;

    float acc[4][4][4];
#pragma unroll
    for (int mt = 0; mt < 4; mt++)
#pragma unroll
        for (int nt = 0; nt < 4; nt++)
#pragma unroll
            for (int i = 0; i < 4; i++) acc[mt][nt][i] = 0.0f;

    const int prow = tid >> 2;          // 0..63
    const int pseg = (tid & 3) * 4;     // word offset

    auto do_prefetch = [&](int c, int st) {
        const uint32_t dbase = sb + (uint32_t)st * STG4 * 4;
        const int bk = c * 16;
#pragma unroll
        for (int pp = 0; pp < 2; pp++) {
            int row = prow + pp * 64;
            size_t soA = (size_t)(m0 + row) * Kw + bk + pseg;
            size_t soB = (size_t)(n0 + row) * Kw + bk + pseg;
            uint32_t d = dbase + (uint32_t)(row * SP3 + pseg) * 4;
            CPA16(d,               Ah  + soA);
            CPA16(d + ARR * 4,     Bth + soB);
            CPA16(d + 2 * ARR * 4, Btl + soB);
        }
        CPA_COMMIT();
    };

    const uint32_t a_rw = (uint32_t)((mb + (lane & 15)) * SP3 + ((lane >> 4) << 2));
    const uint32_t b_rw = (uint32_t)((nb + (lane & 7) + ((lane >> 4) << 3)) * SP3
                                     + (((lane >> 3) & 1) << 2));

    const int nch = K >> 5;
    do_prefetch(0, 0);
    for (int c = 0; c < nch; c++) {
        if (c + 1 < nch) { do_prefetch(c + 1, (c + 1) & 1); CPA_WAIT1(); }
        else             { CPA_WAIT0(); }
        __syncthreads();

        const uint32_t ab = sb + (uint32_t)(c & 1) * STG4 * 4;
#pragma unroll
        for (int ks = 0; ks < 2; ks++) {
            const uint32_t aA = ab + (a_rw + ks * 8) * 4;
            const uint32_t bB = ab + (ARR + b_rw + ks * 8) * 4;
            uint32_t a[4][4], b_hi[4][2], b_lo[4][2];
#pragma unroll
            for (int mt = 0; mt < 4; mt++)
                LDSM4(a[mt][0], a[mt][1], a[mt][2], a[mt][3],
                      aA + mt * 16 * SP3 * 4);
#pragma unroll
            for (int np = 0; np < 2; np++)
                LDSM4(b_hi[2 * np][0], b_hi[2 * np][1],
                      b_hi[2 * np + 1][0], b_hi[2 * np + 1][1],
                      bB + np * 16 * SP3 * 4);
#pragma unroll
            for (int mt = 0; mt < 4; mt++)
#pragma unroll
                for (int nt = 0; nt < 4; nt++)
                    MMA_F16(acc[mt][nt], a[mt], b_hi[nt]);
#pragma unroll
            for (int np = 0; np < 2; np++)
                LDSM4(b_lo[2 * np][0], b_lo[2 * np][1],
                      b_lo[2 * np + 1][0], b_lo[2 * np + 1][1],
                      bB + (ARR + np * 16 * SP3) * 4);
#pragma unroll
            for (int mt = 0; mt < 4; mt++)
#pragma unroll
                for (int nt = 0; nt < 4; nt++)
                    MMA_F16(acc[mt][nt], a[mt], b_lo[nt]);
        }
        __syncthreads();
    }

    // ---- epilogue ----
    const int Nw = N >> 1;
#pragma unroll
    for (int mt = 0; mt < 4; mt++) {
        int row = m0 + mb + mt * 16 + g;
#pragma unroll
        for (int nt = 0; nt < 4; nt++) {
            int col = n0 + nb + nt * 8 + 2 * q;
            float2 bv = *(const float2*)&bias[col];
            float c0 = acc[mt][nt][0] + bv.x, c1 = acc[mt][nt][1] + bv.y;
            float c2 = acc[mt][nt][2] + bv.x, c3 = acc[mt][nt][3] + bv.y;
            if (outMode) {
                size_t w0 = (size_t)row * Nw + (col >> 1);
                size_t w1 = (size_t)(row + 8) * Nw + (col >> 1);
                uint32_t hA, hB, lA, lB;
                F16X2(hA, c1, c0);
                F16X2(hB, c3, c2);
                __half2 ha = *(__half2*)&hA;
                __half2 hb = *(__half2*)&hB;
                float r0 = c0 - __low2float(ha), r1 = c1 - __high2float(ha);
                float r2 = c2 - __low2float(hb), r3 = c3 - __high2float(hb);
                F16X2(lA, r1, r0);
                F16X2(lB, r3, r2);
                Ch[w0] = hA; Cl[w0] = lA;
                Ch[w1] = hB; Cl[w1] = lB;
            } else {
                *(float2*)&Cf[(size_t)row * N + col]       = make_float2(c0, c1);
                *(float2*)&Cf[(size_t)(row + 8) * N + col] = make_float2(c2, c3);
            }
        }
    }
}

// ---------------------------------------------------------------------------
// MMA flash-attention (causal), fp16 operands.
// QK^T: 2-product q_hi * (k_hi + k_lo).
// PV:   single-fp16 P * (v_hi + v_lo).
// Output y as single fp16. grid (Tq/128, B*NH), 256 threads / 8 warps.
// ---------------------------------------------------------------------------
__global__ __launch_bounds__(256, 2)
void attn_mma_kernel(const __half* __restrict__ qkvh_,
                     const __half* __restrict__ qkvl_,
                     __half* __restrict__ yh_)
{
    __shared__ uint32_t sm_[9216];

    const uint32_t* qh32 = (const uint32_t*)qkvh_;
    const uint32_t* ql32 = (const uint32_t*)qkvl_;
    uint32_t* yh32 = (uint32_t*)yh_;

    const int tid  = threadIdx.x;
    const int lane = tid & 31;
    const int w    = tid >> 5;
    const int g    = lane >> 2;
    const int q    = lane & 3;
    const int bh   = blockIdx.y;
    const int b    = bh >> 4;
    const int h    = bh & 15;
    const int qt   = blockIdx.x;
    const int q0   = qt * 128;
    const float scale = 0.125f;

    const size_t base = (size_t)(b * Tq) * 1536;

    // ---- stage Q (hi only), build register fragments ----
    {
        int row = tid >> 3;
        int j4  = (tid & 7) * 4;
#pragma unroll
        for (int p = 0; p < 4; p++) {
            int r = row + 32 * p;
            size_t gw = base + (size_t)(q0 + r) * 1536 + h * 32 + j4;
            *(uint4*)&sm_[r * 36 + j4] = *(const uint4*)(qh32 + gw);
        }
    }
    __syncthreads();
    uint32_t qa[4][4];
    {
        int r0 = 16 * w + g;
#pragma unroll
        for (int ks = 0; ks < 4; ks++) {
            int ba = r0 * 36 + 8 * ks + q;
            qa[ks][0] = sm_[ba];
            qa[ks][1] = sm_[ba + 8 * 36];
            qa[ks][2] = sm_[ba + 4];
            qa[ks][3] = sm_[ba + 8 * 36 + 4];
        }
    }

    float mrow[2] = {-1e30f, -1e30f};
    float lrow[2] = {0.0f, 0.0f};
    float acc[8][4];
#pragma unroll
    for (int nt = 0; nt < 8; nt++)
#pragma unroll
        for (int i = 0; i < 4; i++) acc[nt][i] = 0.0f;

    const int ktmax = 2 * (qt + 1);
    for (int kt = 0; kt < ktmax; kt++) {
        __syncthreads();

        // ---- load K tile hi/lo into [key][dpair] ----
        {
            int row = tid >> 3;
            int j4  = (tid & 7) * 4;
#pragma unroll
            for (int p = 0; p < 2; p++) {
                int r = row + 32 * p;
                size_t gw = base + (size_t)(64 * kt + r) * 1536 + 512 + h * 32 + j4;
                *(uint4*)&sm_[r * 36 + j4]        = *(const uint4*)(qh32 + gw);
                *(uint4*)&sm_[2304 + r * 36 + j4] = *(const uint4*)(ql32 + gw);
            }
        }
        // ---- load V tile + transpose-repack into [d][kpair] ----
        {
            int kp = tid & 31;
            int dg = tid >> 5;
            size_t gv = base + (size_t)(64 * kt + 2 * kp) * 1536 + 1024 + h * 32 + dg * 4;
            uint4 a0 = *(const uint4*)(qh32 + gv);
            uint4 a1 = *(const uint4*)(qh32 + gv + 1536);
            uint4 b0 = *(const uint4*)(ql32 + gv);
            uint4 b1 = *(const uint4*)(ql32 + gv + 1536);
            const uint32_t* a0w = (const uint32_t*)&a0;
            const uint32_t* a1w = (const uint32_t*)&a1;
            const uint32_t* b0w = (const uint32_t*)&b0;
            const uint32_t* b1w = (const uint32_t*)&b1;
#pragma unroll
            for (int j = 0; j < 4; j++) {
                int d = 8 * dg + 2 * j;
                sm_[4608 + d * 36 + kp]       = __byte_perm(a0w[j], a1w[j], 0x5410);
                sm_[4608 + (d + 1) * 36 + kp] = __byte_perm(a0w[j], a1w[j], 0x7632);
                sm_[6912 + d * 36 + kp]       = __byte_perm(b0w[j], b1w[j], 0x5410);
                sm_[6912 + (d + 1) * 36 + kp] = __byte_perm(b0w[j], b1w[j], 0x7632);
            }
        }
        __syncthreads();

        if (64 * kt > q0 + 16 * w + 15) continue;   // warp tile fully masked

        // ---- S = Q K^T, 2-product ----
        float s[8][4];
#pragma unroll
        for (int nt = 0; nt < 8; nt++)
#pragma unroll
            for (int i = 0; i < 4; i++) s[nt][i] = 0.0f;

#pragma unroll
        for (int ks = 0; ks < 4; ks++) {
#pragma unroll
            for (int nt = 0; nt < 8; nt++) {
                int ba = (8 * nt + g) * 36 + 8 * ks + q;
                uint32_t kb_h[2] = { sm_[ba],        sm_[ba + 4] };
                uint32_t kb_l[2] = { sm_[2304 + ba], sm_[2304 + ba + 4] };
                MMA_F16(s[nt], qa[ks], kb_h);
                MMA_F16(s[nt], qa[ks], kb_l);
            }
        }

        // ---- scale + causal mask ----
        const int rowa = q0 + 16 * w + g;
        const int rowb = rowa + 8;
        const bool domask = (64 * kt + 63 > rowa);
#pragma unroll
        for (int nt = 0; nt < 8; nt++) {
#pragma unroll
            for (int i = 0; i < 4; i++) s[nt][i] *= scale;
            if (domask) {
                int kbase = 64 * kt + 8 * nt + 2 * q;
                if (kbase     > rowa) s[nt][0] = -1e30f;
                if (kbase + 1 > rowa) s[nt][1] = -1e30f;
                if (kbase     > rowb) s[nt][2] = -1e30f;
                if (kbase + 1 > rowb) s[nt][3] = -1e30f;
            }
        }

        // ---- online softmax ----
#pragma unroll
        for (int r = 0; r < 2; r++) {
            float mx = -1e30f;
#pragma unroll
            for (int nt = 0; nt < 8; nt++)
                mx = fmaxf(mx, fmaxf(s[nt][2 * r], s[nt][2 * r + 1]));
            mx = fmaxf(mx, __shfl_xor_sync(0xffffffffu, mx, 1));
            mx = fmaxf(mx, __shfl_xor_sync(0xffffffffu, mx, 2));
            float mnew  = fmaxf(mrow[r], mx);
            float alpha = __expf(mrow[r] - mnew);
            float sum = 0.0f;
#pragma unroll
            for (int nt = 0; nt < 8; nt++) {
                s[nt][2 * r]     = __expf(s[nt][2 * r]     - mnew);
                s[nt][2 * r + 1] = __expf(s[nt][2 * r + 1] - mnew);
                sum += s[nt][2 * r] + s[nt][2 * r + 1];
            }
            sum += __shfl_xor_sync(0xffffffffu, sum, 1);
            sum += __shfl_xor_sync(0xffffffffu, sum, 2);
            lrow[r] = lrow[r] * alpha + sum;
            mrow[r] = mnew;
#pragma unroll
            for (int nt = 0; nt < 8; nt++) {
                acc[nt][2 * r]     *= alpha;
                acc[nt][2 * r + 1] *= alpha;
            }
        }

        // ---- PV: single-fp16 P x V(hi,lo) ----
#pragma unroll
        for (int t = 0; t < 4; t++) {
            uint32_t ph[4];
            F16X2(ph[0], s[2*t][1],   s[2*t][0]);
            F16X2(ph[1], s[2*t][3],   s[2*t][2]);
            F16X2(ph[2], s[2*t+1][1], s[2*t+1][0]);
            F16X2(ph[3], s[2*t+1][3], s[2*t+1][2]);
#pragma unroll
            for (int nt = 0; nt < 8; nt++) {
                int ba = (8 * nt + g) * 36 + 8 * t + q;
                uint32_t vb_h[2] = { sm_[4608 + ba], sm_[4608 + ba + 4] };
                uint32_t vb_l[2] = { sm_[6912 + ba], sm_[6912 + ba + 4] };
                MMA_F16(acc[nt], ph, vb_h);
                MMA_F16(acc[nt], ph, vb_l);
            }
        }
    }

    // ---- epilogue: normalize, single-fp16 store of y ----
    {
        float inv0 = 1.0f / lrow[0];
        float inv1 = 1.0f / lrow[1];
        int r = q0 + 16 * w + g;
        size_t w0b = ((size_t)(b * Tq) + r) * 512 + h * 32 + q;
        size_t w1b = w0b + (size_t)8 * 512;
#pragma unroll
        for (int nt = 0; nt < 8; nt++) {
            float v0 = acc[nt][0] * inv0, v1 = acc[nt][1] * inv0;
            float v2 = acc[nt][2] * inv1, v3 = acc[nt][3] * inv1;
            uint32_t o0, o1;
            F16X2(o0, v1, v0);
            F16X2(o1, v3, v2);
            yh32[w0b + 4 * nt] = o0;
            yh32[w1b + 4 * nt] = o1;
        }
    }
}

// ---------------------------------------------------------------------------
// Launch
// ---------------------------------------------------------------------------
extern "C" void kernel_launch(void* const* d_in, const int* in_sizes, int n_in,
                              void* d_out, int out_size)
{
    (void)in_sizes; (void)n_in; (void)out_size;
    const float* x      = (const float*)d_in[0];
    const float* W_attn = (const float*)d_in[1];
    const float* b_attn = (const float*)d_in[2];
    const float* W_proj = (const float*)d_in[3];
    const float* b_proj = (const float*)d_in[4];
    float* out = (float*)d_out;

    __half *x16, *wqh, *wql, *wph, *wpl, *qh, *ql, *yh;
    cudaGetSymbolAddress((void**)&x16, g_x16);
    cudaGetSymbolAddress((void**)&wqh, g_wqh);
    cudaGetSymbolAddress((void**)&wql, g_wql);
    cudaGetSymbolAddress((void**)&wph, g_wph);
    cudaGetSymbolAddress((void**)&wpl, g_wpl);
    cudaGetSymbolAddress((void**)&qh,  g_qkvh);
    cudaGetSymbolAddress((void**)&ql,  g_qkvl);
    cudaGetSymbolAddress((void**)&yh,  g_yh);

    cudaFuncSetAttribute(gemm_mma4_kernel,
                         cudaFuncAttributeMaxDynamicSharedMemorySize, G4_BYTES);

    // 0) pre-convert operands
    cvt_f16_kernel<<<(MQ * Cq / 4 + 255) / 256, 256>>>(x, x16, MQ * Cq / 4);
    cvt_splitT_f16_kernel<<<dim3(C3 / 32, Cq / 32), 256>>>(W_attn, wqh, wql, Cq, C3);
    cvt_splitT_f16_kernel<<<dim3(Cq / 32, Cq / 32), 256>>>(W_proj, wph, wpl, Cq, Cq);

    // 1) qkv(fp16 hi/lo) = x @ W_attn + b_attn
    gemm_mma4_kernel<<<dim3(C3 / 128, MQ / 128), 256, G4_BYTES>>>(
        (const uint32_t*)x16,
        (const uint32_t*)wqh, (const uint32_t*)wql,
        b_attn, nullptr, (uint32_t*)qh, (uint32_t*)ql, MQ, C3, Cq, 1);

    // 2) y(fp16) = causal_attention(qkv)
    attn_mma_kernel<<<dim3(Tq / 128, Bq * NH), 256>>>(qh, ql, yh);

    // 3) out(fp32) = y @ W_proj + b_proj
    gemm_mma4_kernel<<<dim3(Cq / 128, MQ / 128), 256, G4_BYTES>>>(
        (const uint32_t*)yh,
        (const uint32_t*)wph, (const uint32_t*)wpl,
        b_proj, out, nullptr, nullptr, MQ, Cq, Cq, 0);
}

// round 12
// speedup vs baseline: 4.2567x; 1.1442x over previous
#include <cuda_runtime.h>
#include <cuda_bf16.h>
#include <cuda_fp16.h>
#include <math.h>
#include <stdint.h>

// Problem constants
#define Bq   4
#define Tq   2048
#define Cq   1024
#define NH   16
#define HD   64
#define C3   (3 * Cq)          // 3072
#define MQ   (Bq * Tq)         // 8192 rows

// ---------------------------------------------------------------------------
// Scratch (device globals; no runtime allocation allowed)
// ---------------------------------------------------------------------------
__device__ __align__(128) __half g_x16 [(size_t)MQ * Cq];    // x, fp16
__device__ __align__(128) __half g_wqh [(size_t)C3 * Cq];    // W_attn^T hi
__device__ __align__(128) __half g_wql [(size_t)C3 * Cq];    // W_attn^T lo
__device__ __align__(128) __half g_wph [(size_t)Cq * Cq];    // W_proj^T hi
__device__ __align__(128) __half g_wpl [(size_t)Cq * Cq];    // W_proj^T lo
__device__ __align__(128) __half g_qkvh[(size_t)MQ * C3];    // qkv hi
__device__ __align__(128) __half g_qkvl[(size_t)MQ * C3];    // qkv lo
__device__ __align__(128) __half g_yh  [(size_t)MQ * Cq];    // attn out, fp16

// ---------------------------------------------------------------------------
// helpers
// ---------------------------------------------------------------------------
__device__ __forceinline__ uint32_t smem_u32(const void* p) {
    uint32_t a;
    asm("{ .reg .u64 t; cvta.to.shared.u64 t, %1; cvt.u32.u64 %0, t; }"
        : "=r"(a) : "l"(p));
    return a;
}

#define MMA_F16(d, av, bv)                                                     \
  asm volatile("mma.sync.aligned.m16n8k16.row.col.f32.f16.f16.f32 "            \
      "{%0,%1,%2,%3}, {%4,%5,%6,%7}, {%8,%9}, {%0,%1,%2,%3};"                  \
      : "+f"((d)[0]), "+f"((d)[1]), "+f"((d)[2]), "+f"((d)[3])                 \
      : "r"((av)[0]), "r"((av)[1]), "r"((av)[2]), "r"((av)[3]),                \
        "r"((bv)[0]), "r"((bv)[1]))

#define LDSM4(R0, R1, R2, R3, A)                                               \
  asm volatile("ldmatrix.sync.aligned.m8n8.x4.shared.b16 {%0,%1,%2,%3}, [%4];" \
      : "=r"(R0), "=r"(R1), "=r"(R2), "=r"(R3) : "r"(A))

#define LDSM4T(R0, R1, R2, R3, A)                                              \
  asm volatile("ldmatrix.sync.aligned.m8n8.x4.trans.shared.b16 {%0,%1,%2,%3}, [%4];" \
      : "=r"(R0), "=r"(R1), "=r"(R2), "=r"(R3) : "r"(A))

#define CPA16(dst, src)                                                        \
  asm volatile("cp.async.cg.shared.global [%0], [%1], 16;"                     \
      :: "r"(dst), "l"(src) : "memory")
#define CPA_COMMIT() asm volatile("cp.async.commit_group;" ::: "memory")
#define CPA_WAIT1()  asm volatile("cp.async.wait_group 1;" ::: "memory")
#define CPA_WAIT0()  asm volatile("cp.async.wait_group 0;" ::: "memory")

#define F16X2(dst, hi_f, lo_f)                                                 \
  asm("cvt.rn.f16x2.f32 %0, %1, %2;" : "=r"(dst) : "f"(hi_f), "f"(lo_f))

// ---------------------------------------------------------------------------
// cvt kernels
// ---------------------------------------------------------------------------
__global__ void cvt_f16_kernel(const float* __restrict__ a,
                               __half* __restrict__ o, int n4)
{
    int i = blockIdx.x * 256 + threadIdx.x;
    if (i >= n4) return;
    float4 v = ((const float4*)a)[i];
    uint32_t w0, w1;
    F16X2(w0, v.y, v.x);
    F16X2(w1, v.w, v.z);
    uint32_t* o32 = (uint32_t*)o;
    o32[2 * i + 0] = w0;
    o32[2 * i + 1] = w1;
}

// W[K][N] -> out[N][K] fp16 hi/lo
__global__ void cvt_splitT_f16_kernel(const float* __restrict__ w,
                                      __half* __restrict__ th,
                                      __half* __restrict__ tl, int K, int N)
{
    __shared__ float t[32][33];
    int tx = threadIdx.x & 31, ty = threadIdx.x >> 5;
    int k0 = blockIdx.y * 32, n0 = blockIdx.x * 32;
#pragma unroll
    for (int r = 0; r < 4; r++)
        t[ty + 8 * r][tx] = w[(size_t)(k0 + ty + 8 * r) * N + n0 + tx];
    __syncthreads();
#pragma unroll
    for (int r = 0; r < 4; r++) {
        int n = n0 + ty + 8 * r;
        float v = t[tx][ty + 8 * r];
        __half hh = __float2half_rn(v);
        th[(size_t)n * K + k0 + tx] = hh;
        tl[(size_t)n * K + k0 + tx] = __float2half_rn(v - __half2float(hh));
    }
}

// ---------------------------------------------------------------------------
// Pipelined warp-MMA GEMM: C = A[M,K] @ (Bth+Btl)^T + bias   (all fp16 in)
// (unchanged from round 11)
// ---------------------------------------------------------------------------
#define SP3  20
#define ARR  2560
#define STG4 7680
#define G4_BYTES (2 * STG4 * 4)  // 61440

__global__ __launch_bounds__(256, 2)
void gemm_mma4_kernel(const uint32_t* __restrict__ Ah,
                      const uint32_t* __restrict__ Bth, const uint32_t* __restrict__ Btl,
                      const float* __restrict__ bias, float* __restrict__ Cf,
                      uint32_t* __restrict__ Ch, uint32_t* __restrict__ Cl,
                      int M, int N, int K, int outMode)
{
    extern __shared__ uint32_t sm4[];
    const uint32_t sb = smem_u32(sm4);

    const int tid  = threadIdx.x;
    const int lane = tid & 31;
    const int w    = tid >> 5;
    const int m0   = blockIdx.y * 128;
    const int n0   = blockIdx.x * 128;
    const int mb   = (w & 1) * 64;
    const int nb   = (w >> 1) * 32;
    const int g    = lane >> 2;
    const int q    = lane & 3;
    const int Kw   = K >> 1;

    float acc[4][4][4];
#pragma unroll
    for (int mt = 0; mt < 4; mt++)
#pragma unroll
        for (int nt = 0; nt < 4; nt++)
#pragma unroll
            for (int i = 0; i < 4; i++) acc[mt][nt][i] = 0.0f;

    const int prow = tid >> 2;
    const int pseg = (tid & 3) * 4;

    auto do_prefetch = [&](int c, int st) {
        const uint32_t dbase = sb + (uint32_t)st * STG4 * 4;
        const int bk = c * 16;
#pragma unroll
        for (int pp = 0; pp < 2; pp++) {
            int row = prow + pp * 64;
            size_t soA = (size_t)(m0 + row) * Kw + bk + pseg;
            size_t soB = (size_t)(n0 + row) * Kw + bk + pseg;
            uint32_t d = dbase + (uint32_t)(row * SP3 + pseg) * 4;
            CPA16(d,               Ah  + soA);
            CPA16(d + ARR * 4,     Bth + soB);
            CPA16(d + 2 * ARR * 4, Btl + soB);
        }
        CPA_COMMIT();
    };

    const uint32_t a_rw = (uint32_t)((mb + (lane & 15)) * SP3 + ((lane >> 4) << 2));
    const uint32_t b_rw = (uint32_t)((nb + (lane & 7) + ((lane >> 4) << 3)) * SP3
                                     + (((lane >> 3) & 1) << 2));

    const int nch = K >> 5;
    do_prefetch(0, 0);
    for (int c = 0; c < nch; c++) {
        if (c + 1 < nch) { do_prefetch(c + 1, (c + 1) & 1); CPA_WAIT1(); }
        else             { CPA_WAIT0(); }
        __syncthreads();

        const uint32_t ab = sb + (uint32_t)(c & 1) * STG4 * 4;
#pragma unroll
        for (int ks = 0; ks < 2; ks++) {
            const uint32_t aA = ab + (a_rw + ks * 8) * 4;
            const uint32_t bB = ab + (ARR + b_rw + ks * 8) * 4;
            uint32_t a[4][4], b_hi[4][2], b_lo[4][2];
#pragma unroll
            for (int mt = 0; mt < 4; mt++)
                LDSM4(a[mt][0], a[mt][1], a[mt][2], a[mt][3],
                      aA + mt * 16 * SP3 * 4);
#pragma unroll
            for (int np = 0; np < 2; np++)
                LDSM4(b_hi[2 * np][0], b_hi[2 * np][1],
                      b_hi[2 * np + 1][0], b_hi[2 * np + 1][1],
                      bB + np * 16 * SP3 * 4);
#pragma unroll
            for (int mt = 0; mt < 4; mt++)
#pragma unroll
                for (int nt = 0; nt < 4; nt++)
                    MMA_F16(acc[mt][nt], a[mt], b_hi[nt]);
#pragma unroll
            for (int np = 0; np < 2; np++)
                LDSM4(b_lo[2 * np][0], b_lo[2 * np][1],
                      b_lo[2 * np + 1][0], b_lo[2 * np + 1][1],
                      bB + (ARR + np * 16 * SP3) * 4);
#pragma unroll
            for (int mt = 0; mt < 4; mt++)
#pragma unroll
                for (int nt = 0; nt < 4; nt++)
                    MMA_F16(acc[mt][nt], a[mt], b_lo[nt]);
        }
        __syncthreads();
    }

    const int Nw = N >> 1;
#pragma unroll
    for (int mt = 0; mt < 4; mt++) {
        int row = m0 + mb + mt * 16 + g;
#pragma unroll
        for (int nt = 0; nt < 4; nt++) {
            int col = n0 + nb + nt * 8 + 2 * q;
            float2 bv = *(const float2*)&bias[col];
            float c0 = acc[mt][nt][0] + bv.x, c1 = acc[mt][nt][1] + bv.y;
            float c2 = acc[mt][nt][2] + bv.x, c3 = acc[mt][nt][3] + bv.y;
            if (outMode) {
                size_t w0 = (size_t)row * Nw + (col >> 1);
                size_t w1 = (size_t)(row + 8) * Nw + (col >> 1);
                uint32_t hA, hB, lA, lB;
                F16X2(hA, c1, c0);
                F16X2(hB, c3, c2);
                __half2 ha = *(__half2*)&hA;
                __half2 hb = *(__half2*)&hB;
                float r0 = c0 - __low2float(ha), r1 = c1 - __high2float(ha);
                float r2 = c2 - __low2float(hb), r3 = c3 - __high2float(hb);
                F16X2(lA, r1, r0);
                F16X2(lB, r3, r2);
                Ch[w0] = hA; Cl[w0] = lA;
                Ch[w1] = hB; Cl[w1] = lB;
            } else {
                *(float2*)&Cf[(size_t)row * N + col]       = make_float2(c0, c1);
                *(float2*)&Cf[(size_t)(row + 8) * N + col] = make_float2(c2, c3);
            }
        }
    }
}

// ---------------------------------------------------------------------------
// MMA flash-attention (causal), fp16, cp.async double-buffered, ldmatrix frags.
// QK^T: q_hi * (k_hi + k_lo)  -- K natural [key][d] loaded via ldmatrix
// PV:   fp16(P) * (v_hi + v_lo) -- V natural [key][d] via ldmatrix.trans
// grid (Tq/128, B*NH), 256 threads / 8 warps.
// ---------------------------------------------------------------------------
// per-stage smem (words): Kh 0, Kl 2304, Vh 4608, Vl 6912   ([64][36] each)
#define AST 9216
#define A_BYTES (2 * AST * 4)    // 73728

__global__ __launch_bounds__(256, 2)
void attn_mma_kernel(const __half* __restrict__ qkvh_,
                     const __half* __restrict__ qkvl_,
                     __half* __restrict__ yh_)
{
    extern __shared__ uint32_t sma[];
    const uint32_t sb = smem_u32(sma);

    const uint32_t* qh32 = (const uint32_t*)qkvh_;
    const uint32_t* ql32 = (const uint32_t*)qkvl_;
    uint32_t* yh32 = (uint32_t*)yh_;

    const int tid  = threadIdx.x;
    const int lane = tid & 31;
    const int w    = tid >> 5;
    const int g    = lane >> 2;
    const int q    = lane & 3;
    const int bh   = blockIdx.y;
    const int b    = bh >> 4;
    const int h    = bh & 15;
    const int qt   = blockIdx.x;
    const int q0   = qt * 128;
    const float scale = 0.125f;

    const size_t base = (size_t)(b * Tq) * 1536;
    const int ktmax = 2 * (qt + 1);

    // prefetch K/V hi/lo tile kt into stage st (8 cp.async per thread)
    auto prefetch = [&](int kt, int st) {
        const uint32_t dstg = sb + (uint32_t)st * AST * 4;
#pragma unroll
        for (int p = 0; p < 2; p++) {
            int linear = tid + p * 256;          // 0..511
            int row = linear >> 3;               // key 0..63
            int seg = (linear & 7) * 4;          // word offset
            size_t gk = base + (size_t)(64 * kt + row) * 1536 + 512 + h * 32 + seg;
            size_t gv = gk + 512;
            uint32_t d = dstg + (uint32_t)(row * 36 + seg) * 4;
            CPA16(d,            qh32 + gk);      // Kh
            CPA16(d + 2304 * 4, ql32 + gk);      // Kl
            CPA16(d + 4608 * 4, qh32 + gv);      // Vh
            CPA16(d + 6912 * 4, ql32 + gv);      // Vl
        }
        CPA_COMMIT();
    };

    prefetch(0, 0);

    // ---- stage Q (hi only) into stage-1 region, build register fragments ----
    {
        int row = tid >> 3;
        int j4  = (tid & 7) * 4;
#pragma unroll
        for (int p = 0; p < 4; p++) {
            int r = row + 32 * p;
            size_t gw = base + (size_t)(q0 + r) * 1536 + h * 32 + j4;
            *(uint4*)&sma[AST + r * 36 + j4] = *(const uint4*)(qh32 + gw);
        }
    }
    __syncthreads();
    uint32_t qa[4][4];
    {
        // A-frags via ldmatrix from [query][d] (row-major A)
        const uint32_t aA = sb + (uint32_t)(AST + (16 * w + (lane & 15)) * 36
                                            + ((lane >> 4) << 2)) * 4;
#pragma unroll
        for (int ks = 0; ks < 4; ks++)
            LDSM4(qa[ks][0], qa[ks][1], qa[ks][2], qa[ks][3], aA + ks * 8 * 4);
    }

    float mrow[2] = {-1e30f, -1e30f};
    float lrow[2] = {0.0f, 0.0f};
    float acc[8][4];
#pragma unroll
    for (int nt = 0; nt < 8; nt++)
#pragma unroll
        for (int i = 0; i < 4; i++) acc[nt][i] = 0.0f;

    // lane-invariant fragment address components
    const uint32_t k_rw = (uint32_t)(((lane & 7) + ((lane >> 4) << 3)) * 36
                                     + (((lane >> 3) & 1) << 2));
    const uint32_t v_rw = (uint32_t)((lane & 15) * 36 + ((lane >> 4) << 2));

    for (int kt = 0; kt < ktmax; kt++) {
        const int st = kt & 1;
        CPA_WAIT0();
        __syncthreads();
        if (kt + 1 < ktmax) prefetch(kt + 1, st ^ 1);

        if (64 * kt > q0 + 16 * w + 15) continue;   // warp tile fully masked

        const uint32_t stb = sb + (uint32_t)st * AST * 4;

        // ---- S = Q K^T : K-frags via ldmatrix from natural [key][d] ----
        float s[8][4];
#pragma unroll
        for (int nt = 0; nt < 8; nt++)
#pragma unroll
            for (int i = 0; i < 4; i++) s[nt][i] = 0.0f;

#pragma unroll
        for (int ks = 0; ks < 4; ks++) {
            const uint32_t kb_base = stb + (k_rw + ks * 8) * 4;
            uint32_t kb[8][2];
#pragma unroll
            for (int n2 = 0; n2 < 4; n2++)
                LDSM4(kb[2 * n2][0], kb[2 * n2][1],
                      kb[2 * n2 + 1][0], kb[2 * n2 + 1][1],
                      kb_base + n2 * 16 * 36 * 4);
#pragma unroll
            for (int nt = 0; nt < 8; nt++)
                MMA_F16(s[nt], qa[ks], kb[nt]);
#pragma unroll
            for (int n2 = 0; n2 < 4; n2++)
                LDSM4(kb[2 * n2][0], kb[2 * n2][1],
                      kb[2 * n2 + 1][0], kb[2 * n2 + 1][1],
                      kb_base + (2304 + n2 * 16 * 36) * 4);
#pragma unroll
            for (int nt = 0; nt < 8; nt++)
                MMA_F16(s[nt], qa[ks], kb[nt]);
        }

        // ---- scale + causal mask ----
        const int rowa = q0 + 16 * w + g;
        const int rowb = rowa + 8;
        const bool domask = (64 * kt + 63 > rowa);
#pragma unroll
        for (int nt = 0; nt < 8; nt++) {
#pragma unroll
            for (int i = 0; i < 4; i++) s[nt][i] *= scale;
            if (domask) {
                int kbase = 64 * kt + 8 * nt + 2 * q;
                if (kbase     > rowa) s[nt][0] = -1e30f;
                if (kbase + 1 > rowa) s[nt][1] = -1e30f;
                if (kbase     > rowb) s[nt][2] = -1e30f;
                if (kbase + 1 > rowb) s[nt][3] = -1e30f;
            }
        }

        // ---- online softmax ----
#pragma unroll
        for (int r = 0; r < 2; r++) {
            float mx = -1e30f;
#pragma unroll
            for (int nt = 0; nt < 8; nt++)
                mx = fmaxf(mx, fmaxf(s[nt][2 * r], s[nt][2 * r + 1]));
            mx = fmaxf(mx, __shfl_xor_sync(0xffffffffu, mx, 1));
            mx = fmaxf(mx, __shfl_xor_sync(0xffffffffu, mx, 2));
            float mnew  = fmaxf(mrow[r], mx);
            float alpha = __expf(mrow[r] - mnew);
            float sum = 0.0f;
#pragma unroll
            for (int nt = 0; nt < 8; nt++) {
                s[nt][2 * r]     = __expf(s[nt][2 * r]     - mnew);
                s[nt][2 * r + 1] = __expf(s[nt][2 * r + 1] - mnew);
                sum += s[nt][2 * r] + s[nt][2 * r + 1];
            }
            sum += __shfl_xor_sync(0xffffffffu, sum, 1);
            sum += __shfl_xor_sync(0xffffffffu, sum, 2);
            lrow[r] = lrow[r] * alpha + sum;
            mrow[r] = mnew;
#pragma unroll
            for (int nt = 0; nt < 8; nt++) {
                acc[nt][2 * r]     *= alpha;
                acc[nt][2 * r + 1] *= alpha;
            }
        }

        // ---- PV: fp16(P) x V(hi,lo); V-frags via ldmatrix.trans ----
#pragma unroll
        for (int t = 0; t < 4; t++) {
            uint32_t ph[4];
            F16X2(ph[0], s[2*t][1],   s[2*t][0]);
            F16X2(ph[1], s[2*t][3],   s[2*t][2]);
            F16X2(ph[2], s[2*t+1][1], s[2*t+1][0]);
            F16X2(ph[3], s[2*t+1][3], s[2*t+1][2]);
            const uint32_t vb_base = stb + (v_rw + t * 16 * 36) * 4;
            uint32_t vb[8][2];
#pragma unroll
            for (int g2 = 0; g2 < 4; g2++)
                LDSM4T(vb[2 * g2][0], vb[2 * g2][1],
                       vb[2 * g2 + 1][0], vb[2 * g2 + 1][1],
                       vb_base + (4608 + g2 * 8) * 4);
#pragma unroll
            for (int nt = 0; nt < 8; nt++)
                MMA_F16(acc[nt], ph, vb[nt]);
#pragma unroll
            for (int g2 = 0; g2 < 4; g2++)
                LDSM4T(vb[2 * g2][0], vb[2 * g2][1],
                       vb[2 * g2 + 1][0], vb[2 * g2 + 1][1],
                       vb_base + (6912 + g2 * 8) * 4);
#pragma unroll
            for (int nt = 0; nt < 8; nt++)
                MMA_F16(acc[nt], ph, vb[nt]);
        }
    }

    // ---- epilogue: normalize, single-fp16 store of y ----
    {
        float inv0 = 1.0f / lrow[0];
        float inv1 = 1.0f / lrow[1];
        int r = q0 + 16 * w + g;
        size_t w0b = ((size_t)(b * Tq) + r) * 512 + h * 32 + q;
        size_t w1b = w0b + (size_t)8 * 512;
#pragma unroll
        for (int nt = 0; nt < 8; nt++) {
            float v0 = acc[nt][0] * inv0, v1 = acc[nt][1] * inv0;
            float v2 = acc[nt][2] * inv1, v3 = acc[nt][3] * inv1;
            uint32_t o0, o1;
            F16X2(o0, v1, v0);
            F16X2(o1, v3, v2);
            yh32[w0b + 4 * nt] = o0;
            yh32[w1b + 4 * nt] = o1;
        }
    }
}

// ---------------------------------------------------------------------------
// Launch
// ---------------------------------------------------------------------------
extern "C" void kernel_launch(void* const* d_in, const int* in_sizes, int n_in,
                              void* d_out, int out_size)
{
    (void)in_sizes; (void)n_in; (void)out_size;
    const float* x      = (const float*)d_in[0];
    const float* W_attn = (const float*)d_in[1];
    const float* b_attn = (const float*)d_in[2];
    const float* W_proj = (const float*)d_in[3];
    const float* b_proj = (const float*)d_in[4];
    float* out = (float*)d_out;

    __half *x16, *wqh, *wql, *wph, *wpl, *qh, *ql, *yh;
    cudaGetSymbolAddress((void**)&x16, g_x16);
    cudaGetSymbolAddress((void**)&wqh, g_wqh);
    cudaGetSymbolAddress((void**)&wql, g_wql);
    cudaGetSymbolAddress((void**)&wph, g_wph);
    cudaGetSymbolAddress((void**)&wpl, g_wpl);
    cudaGetSymbolAddress((void**)&qh,  g_qkvh);
    cudaGetSymbolAddress((void**)&ql,  g_qkvl);
    cudaGetSymbolAddress((void**)&yh,  g_yh);

    cudaFuncSetAttribute(gemm_mma4_kernel,
                         cudaFuncAttributeMaxDynamicSharedMemorySize, G4_BYTES);
    cudaFuncSetAttribute(attn_mma_kernel,
                         cudaFuncAttributeMaxDynamicSharedMemorySize, A_BYTES);

    // 0) pre-convert operands
    cvt_f16_kernel<<<(MQ * Cq / 4 + 255) / 256, 256>>>(x, x16, MQ * Cq / 4);
    cvt_splitT_f16_kernel<<<dim3(C3 / 32, Cq / 32), 256>>>(W_attn, wqh, wql, Cq, C3);
    cvt_splitT_f16_kernel<<<dim3(Cq / 32, Cq / 32), 256>>>(W_proj, wph, wpl, Cq, Cq);

    // 1) qkv(fp16 hi/lo) = x @ W_attn + b_attn
    gemm_mma4_kernel<<<dim3(C3 / 128, MQ / 128), 256, G4_BYTES>>>(
        (const uint32_t*)x16,
        (const uint32_t*)wqh, (const uint32_t*)wql,
        b_attn, nullptr, (uint32_t*)qh, (uint32_t*)ql, MQ, C3, Cq, 1);

    // 2) y(fp16) = causal_attention(qkv)
    attn_mma_kernel<<<dim3(Tq / 128, Bq * NH), 256, A_BYTES>>>(qh, ql, yh);

    // 3) out(fp32) = y @ W_proj + b_proj
    gemm_mma4_kernel<<<dim3(Cq / 128, MQ / 128), 256, G4_BYTES>>>(
        (const uint32_t*)yh,
        (const uint32_t*)wph, (const uint32_t*)wpl,
        b_proj, out, nullptr, nullptr, MQ, Cq, Cq, 0);
}

// round 13
// speedup vs baseline: 4.4844x; 1.0535x over previous
#include <cuda_runtime.h>
#include <cuda_bf16.h>
#include <cuda_fp16.h>
#include <math.h>
#include <stdint.h>

// Problem constants
#define Bq   4
#define Tq   2048
#define Cq   1024
#define NH   16
#define HD   64
#define C3   (3 * Cq)          // 3072
#define MQ   (Bq * Tq)         // 8192 rows

// ---------------------------------------------------------------------------
// Scratch (device globals; no runtime allocation allowed)
// ---------------------------------------------------------------------------
__device__ __align__(128) __half g_x16 [(size_t)MQ * Cq];    // x, fp16
__device__ __align__(128) __half g_wqh [(size_t)C3 * Cq];    // W_attn^T hi
__device__ __align__(128) __half g_wql [(size_t)C3 * Cq];    // W_attn^T lo
__device__ __align__(128) __half g_wph [(size_t)Cq * Cq];    // W_proj^T hi
__device__ __align__(128) __half g_wpl [(size_t)Cq * Cq];    // W_proj^T lo
__device__ __align__(128) __half g_qkvh[(size_t)MQ * C3];    // qkv hi
__device__ __align__(128) __half g_qkvl[(size_t)MQ * C3];    // qkv lo
__device__ __align__(128) __half g_yh  [(size_t)MQ * Cq];    // attn out, fp16

// ---------------------------------------------------------------------------
// helpers
// ---------------------------------------------------------------------------
__device__ __forceinline__ uint32_t smem_u32(const void* p) {
    uint32_t a;
    asm("{ .reg .u64 t; cvta.to.shared.u64 t, %1; cvt.u32.u64 %0, t; }"
        : "=r"(a) : "l"(p));
    return a;
}

#define MMA_F16(d, av, bv)                                                     \
  asm volatile("mma.sync.aligned.m16n8k16.row.col.f32.f16.f16.f32 "            \
      "{%0,%1,%2,%3}, {%4,%5,%6,%7}, {%8,%9}, {%0,%1,%2,%3};"                  \
      : "+f"((d)[0]), "+f"((d)[1]), "+f"((d)[2]), "+f"((d)[3])                 \
      : "r"((av)[0]), "r"((av)[1]), "r"((av)[2]), "r"((av)[3]),                \
        "r"((bv)[0]), "r"((bv)[1]))

#define LDSM4(R0, R1, R2, R3, A)                                               \
  asm volatile("ldmatrix.sync.aligned.m8n8.x4.shared.b16 {%0,%1,%2,%3}, [%4];" \
      : "=r"(R0), "=r"(R1), "=r"(R2), "=r"(R3) : "r"(A))

#define LDSM4T(R0, R1, R2, R3, A)                                              \
  asm volatile("ldmatrix.sync.aligned.m8n8.x4.trans.shared.b16 {%0,%1,%2,%3}, [%4];" \
      : "=r"(R0), "=r"(R1), "=r"(R2), "=r"(R3) : "r"(A))

#define CPA16(dst, src)                                                        \
  asm volatile("cp.async.cg.shared.global [%0], [%1], 16;"                     \
      :: "r"(dst), "l"(src) : "memory")
#define CPA_COMMIT() asm volatile("cp.async.commit_group;" ::: "memory")
#define CPA_WAIT1()  asm volatile("cp.async.wait_group 1;" ::: "memory")
#define CPA_WAIT0()  asm volatile("cp.async.wait_group 0;" ::: "memory")

#define F16X2(dst, hi_f, lo_f)                                                 \
  asm("cvt.rn.f16x2.f32 %0, %1, %2;" : "=r"(dst) : "f"(hi_f), "f"(lo_f))

// ---------------------------------------------------------------------------
// cvt kernels
// ---------------------------------------------------------------------------
__global__ void cvt_f16_kernel(const float* __restrict__ a,
                               __half* __restrict__ o, int n4)
{
    int i = blockIdx.x * 256 + threadIdx.x;
    if (i >= n4) return;
    float4 v = ((const float4*)a)[i];
    uint32_t w0, w1;
    F16X2(w0, v.y, v.x);
    F16X2(w1, v.w, v.z);
    uint32_t* o32 = (uint32_t*)o;
    o32[2 * i + 0] = w0;
    o32[2 * i + 1] = w1;
}

// W[K][N] -> out[N][K] fp16 hi/lo
__global__ void cvt_splitT_f16_kernel(const float* __restrict__ w,
                                      __half* __restrict__ th,
                                      __half* __restrict__ tl, int K, int N)
{
    __shared__ float t[32][33];
    int tx = threadIdx.x & 31, ty = threadIdx.x >> 5;
    int k0 = blockIdx.y * 32, n0 = blockIdx.x * 32;
#pragma unroll
    for (int r = 0; r < 4; r++)
        t[ty + 8 * r][tx] = w[(size_t)(k0 + ty + 8 * r) * N + n0 + tx];
    __syncthreads();
#pragma unroll
    for (int r = 0; r < 4; r++) {
        int n = n0 + ty + 8 * r;
        float v = t[tx][ty + 8 * r];
        __half hh = __float2half_rn(v);
        th[(size_t)n * K + k0 + tx] = hh;
        tl[(size_t)n * K + k0 + tx] = __float2half_rn(v - __half2float(hh));
    }
}

// ---------------------------------------------------------------------------
// Pipelined warp-MMA GEMM: C = A[M,K] @ (Bth+Btl)^T + bias   (all fp16 in)
// 3-stage cp.async pipeline, ONE __syncthreads per K-chunk.
// ---------------------------------------------------------------------------
#define SP3  20
#define ARR  2560
#define STG4 7680
#define G4_BYTES (3 * STG4 * 4)  // 92160

__global__ __launch_bounds__(256, 2)
void gemm_mma4_kernel(const uint32_t* __restrict__ Ah,
                      const uint32_t* __restrict__ Bth, const uint32_t* __restrict__ Btl,
                      const float* __restrict__ bias, float* __restrict__ Cf,
                      uint32_t* __restrict__ Ch, uint32_t* __restrict__ Cl,
                      int M, int N, int K, int outMode)
{
    extern __shared__ uint32_t sm4[];
    const uint32_t sb = smem_u32(sm4);

    const int tid  = threadIdx.x;
    const int lane = tid & 31;
    const int w    = tid >> 5;
    const int m0   = blockIdx.y * 128;
    const int n0   = blockIdx.x * 128;
    const int mb   = (w & 1) * 64;
    const int nb   = (w >> 1) * 32;
    const int g    = lane >> 2;
    const int q    = lane & 3;
    const int Kw   = K >> 1;

    float acc[4][4][4];
#pragma unroll
    for (int mt = 0; mt < 4; mt++)
#pragma unroll
        for (int nt = 0; nt < 4; nt++)
#pragma unroll
            for (int i = 0; i < 4; i++) acc[mt][nt][i] = 0.0f;

    const int prow = tid >> 2;
    const int pseg = (tid & 3) * 4;

    auto do_prefetch = [&](int c, int st) {
        const uint32_t dbase = sb + (uint32_t)st * STG4 * 4;
        const int bk = c * 16;
#pragma unroll
        for (int pp = 0; pp < 2; pp++) {
            int row = prow + pp * 64;
            size_t soA = (size_t)(m0 + row) * Kw + bk + pseg;
            size_t soB = (size_t)(n0 + row) * Kw + bk + pseg;
            uint32_t d = dbase + (uint32_t)(row * SP3 + pseg) * 4;
            CPA16(d,               Ah  + soA);
            CPA16(d + ARR * 4,     Bth + soB);
            CPA16(d + 2 * ARR * 4, Btl + soB);
        }
        CPA_COMMIT();
    };

    const uint32_t a_rw = (uint32_t)((mb + (lane & 15)) * SP3 + ((lane >> 4) << 2));
    const uint32_t b_rw = (uint32_t)((nb + (lane & 7) + ((lane >> 4) << 3)) * SP3
                                     + (((lane >> 3) & 1) << 2));

    const int nch = K >> 5;
    do_prefetch(0, 0);
    do_prefetch(1, 1);
    int s_cur = 0, s_nxt = 2;       // stage of chunk c; stage for chunk c+2
    for (int c = 0; c < nch; c++) {
        if (c + 1 < nch) CPA_WAIT1(); else CPA_WAIT0();
        __syncthreads();
        if (c + 2 < nch) do_prefetch(c + 2, s_nxt);

        const uint32_t ab = sb + (uint32_t)s_cur * STG4 * 4;
#pragma unroll
        for (int ks = 0; ks < 2; ks++) {
            const uint32_t aA = ab + (a_rw + ks * 8) * 4;
            const uint32_t bB = ab + (ARR + b_rw + ks * 8) * 4;
            uint32_t a[4][4], b_hi[4][2], b_lo[4][2];
#pragma unroll
            for (int mt = 0; mt < 4; mt++)
                LDSM4(a[mt][0], a[mt][1], a[mt][2], a[mt][3],
                      aA + mt * 16 * SP3 * 4);
#pragma unroll
            for (int np = 0; np < 2; np++)
                LDSM4(b_hi[2 * np][0], b_hi[2 * np][1],
                      b_hi[2 * np + 1][0], b_hi[2 * np + 1][1],
                      bB + np * 16 * SP3 * 4);
#pragma unroll
            for (int mt = 0; mt < 4; mt++)
#pragma unroll
                for (int nt = 0; nt < 4; nt++)
                    MMA_F16(acc[mt][nt], a[mt], b_hi[nt]);
#pragma unroll
            for (int np = 0; np < 2; np++)
                LDSM4(b_lo[2 * np][0], b_lo[2 * np][1],
                      b_lo[2 * np + 1][0], b_lo[2 * np + 1][1],
                      bB + (ARR + np * 16 * SP3) * 4);
#pragma unroll
            for (int mt = 0; mt < 4; mt++)
#pragma unroll
                for (int nt = 0; nt < 4; nt++)
                    MMA_F16(acc[mt][nt], a[mt], b_lo[nt]);
        }
        s_cur = (s_cur == 2) ? 0 : s_cur + 1;
        s_nxt = (s_nxt == 2) ? 0 : s_nxt + 1;
    }

    const int Nw = N >> 1;
#pragma unroll
    for (int mt = 0; mt < 4; mt++) {
        int row = m0 + mb + mt * 16 + g;
#pragma unroll
        for (int nt = 0; nt < 4; nt++) {
            int col = n0 + nb + nt * 8 + 2 * q;
            float2 bv = *(const float2*)&bias[col];
            float c0 = acc[mt][nt][0] + bv.x, c1 = acc[mt][nt][1] + bv.y;
            float c2 = acc[mt][nt][2] + bv.x, c3 = acc[mt][nt][3] + bv.y;
            if (outMode) {
                size_t w0 = (size_t)row * Nw + (col >> 1);
                size_t w1 = (size_t)(row + 8) * Nw + (col >> 1);
                uint32_t hA, hB, lA, lB;
                F16X2(hA, c1, c0);
                F16X2(hB, c3, c2);
                __half2 ha = *(__half2*)&hA;
                __half2 hb = *(__half2*)&hB;
                float r0 = c0 - __low2float(ha), r1 = c1 - __high2float(ha);
                float r2 = c2 - __low2float(hb), r3 = c3 - __high2float(hb);
                F16X2(lA, r1, r0);
                F16X2(lB, r3, r2);
                Ch[w0] = hA; Cl[w0] = lA;
                Ch[w1] = hB; Cl[w1] = lB;
            } else {
                *(float2*)&Cf[(size_t)row * N + col]       = make_float2(c0, c1);
                *(float2*)&Cf[(size_t)(row + 8) * N + col] = make_float2(c2, c3);
            }
        }
    }
}

// ---------------------------------------------------------------------------
// MMA flash-attention (causal), fp16, cp.async double-buffered, ldmatrix frags.
// QK^T: q_hi * (k_hi + k_lo).   PV: fp16(P) * v_hi (single product).
// q-tiles processed in DESCENDING order (heaviest CTAs first).
// ---------------------------------------------------------------------------
// per-stage smem (words): Kh 0, Kl 2304, Vh 4608   ([64][36] each)
#define AST 6912
#define A_BYTES (2 * AST * 4)    // 55296

__global__ __launch_bounds__(256, 2)
void attn_mma_kernel(const __half* __restrict__ qkvh_,
                     const __half* __restrict__ qkvl_,
                     __half* __restrict__ yh_)
{
    extern __shared__ uint32_t sma[];
    const uint32_t sb = smem_u32(sma);

    const uint32_t* qh32 = (const uint32_t*)qkvh_;
    const uint32_t* ql32 = (const uint32_t*)qkvl_;
    uint32_t* yh32 = (uint32_t*)yh_;

    const int tid  = threadIdx.x;
    const int lane = tid & 31;
    const int w    = tid >> 5;
    const int g    = lane >> 2;
    const int q    = lane & 3;
    const int bh   = blockIdx.y;
    const int b    = bh >> 4;
    const int h    = bh & 15;
    const int qt   = gridDim.x - 1 - blockIdx.x;   // heavy tiles first
    const int q0   = qt * 128;
    const float scale = 0.125f;

    const size_t base = (size_t)(b * Tq) * 1536;
    const int ktmax = 2 * (qt + 1);

    // prefetch K(hi,lo) + V(hi) tile kt into stage st
    auto prefetch = [&](int kt, int st) {
        const uint32_t dstg = sb + (uint32_t)st * AST * 4;
#pragma unroll
        for (int p = 0; p < 2; p++) {
            int linear = tid + p * 256;          // 0..511
            int row = linear >> 3;               // key 0..63
            int seg = (linear & 7) * 4;          // word offset
            size_t gk = base + (size_t)(64 * kt + row) * 1536 + 512 + h * 32 + seg;
            size_t gv = gk + 512;
            uint32_t d = dstg + (uint32_t)(row * 36 + seg) * 4;
            CPA16(d,            qh32 + gk);      // Kh
            CPA16(d + 2304 * 4, ql32 + gk);      // Kl
            CPA16(d + 4608 * 4, qh32 + gv);      // Vh
        }
        CPA_COMMIT();
    };

    prefetch(0, 0);

    // ---- stage Q (hi only) into stage-1 region, build register fragments ----
    {
        int row = tid >> 3;
        int j4  = (tid & 7) * 4;
#pragma unroll
        for (int p = 0; p < 4; p++) {
            int r = row + 32 * p;
            size_t gw = base + (size_t)(q0 + r) * 1536 + h * 32 + j4;
            *(uint4*)&sma[AST + r * 36 + j4] = *(const uint4*)(qh32 + gw);
        }
    }
    __syncthreads();
    uint32_t qa[4][4];
    {
        const uint32_t aA = sb + (uint32_t)(AST + (16 * w + (lane & 15)) * 36
                                            + ((lane >> 4) << 2)) * 4;
#pragma unroll
        for (int ks = 0; ks < 4; ks++)
            LDSM4(qa[ks][0], qa[ks][1], qa[ks][2], qa[ks][3], aA + ks * 8 * 4);
    }

    float mrow[2] = {-1e30f, -1e30f};
    float lrow[2] = {0.0f, 0.0f};
    float acc[8][4];
#pragma unroll
    for (int nt = 0; nt < 8; nt++)
#pragma unroll
        for (int i = 0; i < 4; i++) acc[nt][i] = 0.0f;

    const uint32_t k_rw = (uint32_t)(((lane & 7) + ((lane >> 4) << 3)) * 36
                                     + (((lane >> 3) & 1) << 2));
    const uint32_t v_rw = (uint32_t)((lane & 15) * 36 + ((lane >> 4) << 2));

    for (int kt = 0; kt < ktmax; kt++) {
        const int st = kt & 1;
        CPA_WAIT0();
        __syncthreads();
        if (kt + 1 < ktmax) prefetch(kt + 1, st ^ 1);

        if (64 * kt > q0 + 16 * w + 15) continue;   // warp tile fully masked

        const uint32_t stb = sb + (uint32_t)st * AST * 4;

        // ---- S = Q K^T ----
        float s[8][4];
#pragma unroll
        for (int nt = 0; nt < 8; nt++)
#pragma unroll
            for (int i = 0; i < 4; i++) s[nt][i] = 0.0f;

#pragma unroll
        for (int ks = 0; ks < 4; ks++) {
            const uint32_t kb_base = stb + (k_rw + ks * 8) * 4;
            uint32_t kb[8][2];
#pragma unroll
            for (int n2 = 0; n2 < 4; n2++)
                LDSM4(kb[2 * n2][0], kb[2 * n2][1],
                      kb[2 * n2 + 1][0], kb[2 * n2 + 1][1],
                      kb_base + n2 * 16 * 36 * 4);
#pragma unroll
            for (int nt = 0; nt < 8; nt++)
                MMA_F16(s[nt], qa[ks], kb[nt]);
#pragma unroll
            for (int n2 = 0; n2 < 4; n2++)
                LDSM4(kb[2 * n2][0], kb[2 * n2][1],
                      kb[2 * n2 + 1][0], kb[2 * n2 + 1][1],
                      kb_base + (2304 + n2 * 16 * 36) * 4);
#pragma unroll
            for (int nt = 0; nt < 8; nt++)
                MMA_F16(s[nt], qa[ks], kb[nt]);
        }

        // ---- scale + causal mask ----
        const int rowa = q0 + 16 * w + g;
        const int rowb = rowa + 8;
        const bool domask = (64 * kt + 63 > rowa);
#pragma unroll
        for (int nt = 0; nt < 8; nt++) {
#pragma unroll
            for (int i = 0; i < 4; i++) s[nt][i] *= scale;
            if (domask) {
                int kbase = 64 * kt + 8 * nt + 2 * q;
                if (kbase     > rowa) s[nt][0] = -1e30f;
                if (kbase + 1 > rowa) s[nt][1] = -1e30f;
                if (kbase     > rowb) s[nt][2] = -1e30f;
                if (kbase + 1 > rowb) s[nt][3] = -1e30f;
            }
        }

        // ---- online softmax ----
#pragma unroll
        for (int r = 0; r < 2; r++) {
            float mx = -1e30f;
#pragma unroll
            for (int nt = 0; nt < 8; nt++)
                mx = fmaxf(mx, fmaxf(s[nt][2 * r], s[nt][2 * r + 1]));
            mx = fmaxf(mx, __shfl_xor_sync(0xffffffffu, mx, 1));
            mx = fmaxf(mx, __shfl_xor_sync(0xffffffffu, mx, 2));
            float mnew  = fmaxf(mrow[r], mx);
            float alpha = __expf(mrow[r] - mnew);
            float sum = 0.0f;
#pragma unroll
            for (int nt = 0; nt < 8; nt++) {
                s[nt][2 * r]     = __expf(s[nt][2 * r]     - mnew);
                s[nt][2 * r + 1] = __expf(s[nt][2 * r + 1] - mnew);
                sum += s[nt][2 * r] + s[nt][2 * r + 1];
            }
            sum += __shfl_xor_sync(0xffffffffu, sum, 1);
            sum += __shfl_xor_sync(0xffffffffu, sum, 2);
            lrow[r] = lrow[r] * alpha + sum;
            mrow[r] = mnew;
#pragma unroll
            for (int nt = 0; nt < 8; nt++) {
                acc[nt][2 * r]     *= alpha;
                acc[nt][2 * r + 1] *= alpha;
            }
        }

        // ---- PV: fp16(P) x V_hi (single product); V via ldmatrix.trans ----
#pragma unroll
        for (int t = 0; t < 4; t++) {
            uint32_t ph[4];
            F16X2(ph[0], s[2*t][1],   s[2*t][0]);
            F16X2(ph[1], s[2*t][3],   s[2*t][2]);
            F16X2(ph[2], s[2*t+1][1], s[2*t+1][0]);
            F16X2(ph[3], s[2*t+1][3], s[2*t+1][2]);
            const uint32_t vb_base = stb + (v_rw + t * 16 * 36) * 4;
            uint32_t vb[8][2];
#pragma unroll
            for (int g2 = 0; g2 < 4; g2++)
                LDSM4T(vb[2 * g2][0], vb[2 * g2][1],
                       vb[2 * g2 + 1][0], vb[2 * g2 + 1][1],
                       vb_base + (4608 + g2 * 8) * 4);
#pragma unroll
            for (int nt = 0; nt < 8; nt++)
                MMA_F16(acc[nt], ph, vb[nt]);
        }
    }

    // ---- epilogue: normalize, single-fp16 store of y ----
    {
        float inv0 = 1.0f / lrow[0];
        float inv1 = 1.0f / lrow[1];
        int r = q0 + 16 * w + g;
        size_t w0b = ((size_t)(b * Tq) + r) * 512 + h * 32 + q;
        size_t w1b = w0b + (size_t)8 * 512;
#pragma unroll
        for (int nt = 0; nt < 8; nt++) {
            float v0 = acc[nt][0] * inv0, v1 = acc[nt][1] * inv0;
            float v2 = acc[nt][2] * inv1, v3 = acc[nt][3] * inv1;
            uint32_t o0, o1;
            F16X2(o0, v1, v0);
            F16X2(o1, v3, v2);
            yh32[w0b + 4 * nt] = o0;
            yh32[w1b + 4 * nt] = o1;
        }
    }
}

// ---------------------------------------------------------------------------
// Launch
// ---------------------------------------------------------------------------
extern "C" void kernel_launch(void* const* d_in, const int* in_sizes, int n_in,
                              void* d_out, int out_size)
{
    (void)in_sizes; (void)n_in; (void)out_size;
    const float* x      = (const float*)d_in[0];
    const float* W_attn = (const float*)d_in[1];
    const float* b_attn = (const float*)d_in[2];
    const float* W_proj = (const float*)d_in[3];
    const float* b_proj = (const float*)d_in[4];
    float* out = (float*)d_out;

    __half *x16, *wqh, *wql, *wph, *wpl, *qh, *ql, *yh;
    cudaGetSymbolAddress((void**)&x16, g_x16);
    cudaGetSymbolAddress((void**)&wqh, g_wqh);
    cudaGetSymbolAddress((void**)&wql, g_wql);
    cudaGetSymbolAddress((void**)&wph, g_wph);
    cudaGetSymbolAddress((void**)&wpl, g_wpl);
    cudaGetSymbolAddress((void**)&qh,  g_qkvh);
    cudaGetSymbolAddress((void**)&ql,  g_qkvl);
    cudaGetSymbolAddress((void**)&yh,  g_yh);

    cudaFuncSetAttribute(gemm_mma4_kernel,
                         cudaFuncAttributeMaxDynamicSharedMemorySize, G4_BYTES);
    cudaFuncSetAttribute(attn_mma_kernel,
                         cudaFuncAttributeMaxDynamicSharedMemorySize, A_BYTES);

    // 0) pre-convert operands
    cvt_f16_kernel<<<(MQ * Cq / 4 + 255) / 256, 256>>>(x, x16, MQ * Cq / 4);
    cvt_splitT_f16_kernel<<<dim3(C3 / 32, Cq / 32), 256>>>(W_attn, wqh, wql, Cq, C3);
    cvt_splitT_f16_kernel<<<dim3(Cq / 32, Cq / 32), 256>>>(W_proj, wph, wpl, Cq, Cq);

    // 1) qkv(fp16 hi/lo) = x @ W_attn + b_attn
    gemm_mma4_kernel<<<dim3(C3 / 128, MQ / 128), 256, G4_BYTES>>>(
        (const uint32_t*)x16,
        (const uint32_t*)wqh, (const uint32_t*)wql,
        b_attn, nullptr, (uint32_t*)qh, (uint32_t*)ql, MQ, C3, Cq, 1);

    // 2) y(fp16) = causal_attention(qkv)
    attn_mma_kernel<<<dim3(Tq / 128, Bq * NH), 256, A_BYTES>>>(qh, ql, yh);

    // 3) out(fp32) = y @ W_proj + b_proj
    gemm_mma4_kernel<<<dim3(Cq / 128, MQ / 128), 256, G4_BYTES>>>(
        (const uint32_t*)yh,
        (const uint32_t*)wph, (const uint32_t*)wpl,
        b_proj, out, nullptr, nullptr, MQ, Cq, Cq, 0);
}

// round 14
// speedup vs baseline: 4.8048x; 1.0714x over previous
#include <cuda_runtime.h>
#include <cuda_bf16.h>
#include <cuda_fp16.h>
#include <math.h>
#include <stdint.h>

// Problem constants
#define Bq   4
#define Tq   2048
#define Cq   1024
#define NH   16
#define HD   64
#define C3   (3 * Cq)          // 3072
#define MQ   (Bq * Tq)         // 8192 rows

// ---------------------------------------------------------------------------
// Scratch (device globals; no runtime allocation allowed)
// ---------------------------------------------------------------------------
__device__ __align__(128) __half g_x16 [(size_t)MQ * Cq];    // x, fp16
__device__ __align__(128) __half g_wqh [(size_t)C3 * Cq];    // W_attn^T hi
__device__ __align__(128) __half g_wql [(size_t)C3 * Cq];    // W_attn^T lo
__device__ __align__(128) __half g_wph [(size_t)Cq * Cq];    // W_proj^T hi
__device__ __align__(128) __half g_wpl [(size_t)Cq * Cq];    // W_proj^T lo
__device__ __align__(128) __half g_qkvh[(size_t)MQ * C3];    // qkv hi
__device__ __align__(128) __half g_qkvl[(size_t)MQ * C3];    // qkv lo
__device__ __align__(128) __half g_yh  [(size_t)MQ * Cq];    // attn out, fp16

// ---------------------------------------------------------------------------
// helpers
// ---------------------------------------------------------------------------
__device__ __forceinline__ uint32_t smem_u32(const void* p) {
    uint32_t a;
    asm("{ .reg .u64 t; cvta.to.shared.u64 t, %1; cvt.u32.u64 %0, t; }"
        : "=r"(a) : "l"(p));
    return a;
}

#define MMA_F16(d, av, bv)                                                     \
  asm volatile("mma.sync.aligned.m16n8k16.row.col.f32.f16.f16.f32 "            \
      "{%0,%1,%2,%3}, {%4,%5,%6,%7}, {%8,%9}, {%0,%1,%2,%3};"                  \
      : "+f"((d)[0]), "+f"((d)[1]), "+f"((d)[2]), "+f"((d)[3])                 \
      : "r"((av)[0]), "r"((av)[1]), "r"((av)[2]), "r"((av)[3]),                \
        "r"((bv)[0]), "r"((bv)[1]))

#define LDSM4(R0, R1, R2, R3, A)                                               \
  asm volatile("ldmatrix.sync.aligned.m8n8.x4.shared.b16 {%0,%1,%2,%3}, [%4];" \
      : "=r"(R0), "=r"(R1), "=r"(R2), "=r"(R3) : "r"(A))

#define LDSM4T(R0, R1, R2, R3, A)                                              \
  asm volatile("ldmatrix.sync.aligned.m8n8.x4.trans.shared.b16 {%0,%1,%2,%3}, [%4];" \
      : "=r"(R0), "=r"(R1), "=r"(R2), "=r"(R3) : "r"(A))

#define CPA16(dst, src)                                                        \
  asm volatile("cp.async.cg.shared.global [%0], [%1], 16;"                     \
      :: "r"(dst), "l"(src) : "memory")
#define CPA_COMMIT() asm volatile("cp.async.commit_group;" ::: "memory")
#define CPA_WAIT0()  asm volatile("cp.async.wait_group 0;" ::: "memory")

#define F16X2(dst, hi_f, lo_f)                                                 \
  asm("cvt.rn.f16x2.f32 %0, %1, %2;" : "=r"(dst) : "f"(hi_f), "f"(lo_f))

// ---------------------------------------------------------------------------
// cvt kernels
// ---------------------------------------------------------------------------
__global__ void cvt_f16_kernel(const float* __restrict__ a,
                               __half* __restrict__ o, int n4)
{
    int i = blockIdx.x * 256 + threadIdx.x;
    if (i >= n4) return;
    float4 v = ((const float4*)a)[i];
    uint32_t w0, w1;
    F16X2(w0, v.y, v.x);
    F16X2(w1, v.w, v.z);
    uint32_t* o32 = (uint32_t*)o;
    o32[2 * i + 0] = w0;
    o32[2 * i + 1] = w1;
}

// W[K][N] -> out[N][K] fp16 hi/lo
__global__ void cvt_splitT_f16_kernel(const float* __restrict__ w,
                                      __half* __restrict__ th,
                                      __half* __restrict__ tl, int K, int N)
{
    __shared__ float t[32][33];
    int tx = threadIdx.x & 31, ty = threadIdx.x >> 5;
    int k0 = blockIdx.y * 32, n0 = blockIdx.x * 32;
#pragma unroll
    for (int r = 0; r < 4; r++)
        t[ty + 8 * r][tx] = w[(size_t)(k0 + ty + 8 * r) * N + n0 + tx];
    __syncthreads();
#pragma unroll
    for (int r = 0; r < 4; r++) {
        int n = n0 + ty + 8 * r;
        float v = t[tx][ty + 8 * r];
        __half hh = __float2half_rn(v);
        th[(size_t)n * K + k0 + tx] = hh;
        tl[(size_t)n * K + k0 + tx] = __float2half_rn(v - __half2float(hh));
    }
}

// ---------------------------------------------------------------------------
// Pipelined warp-MMA GEMM: C = A[M,K] @ (Bth+Btl)^T + bias   (all fp16 in)
// K-chunk 64 (4 k16-steps), 2-stage cp.async, ONE __syncthreads per chunk.
// 128x128 CTA / 8 warps / 64x32 warp tile.
// ---------------------------------------------------------------------------
#define SPW  36                  // words per smem row (32 data + 4 pad)
#define ARR2 4608                // words per array (128*36)
#define STG5 13824               // words per stage (3 arrays)
#define G4_BYTES (2 * STG5 * 4)  // 110592

__global__ __launch_bounds__(256, 2)
void gemm_mma4_kernel(const uint32_t* __restrict__ Ah,
                      const uint32_t* __restrict__ Bth, const uint32_t* __restrict__ Btl,
                      const float* __restrict__ bias, float* __restrict__ Cf,
                      uint32_t* __restrict__ Ch, uint32_t* __restrict__ Cl,
                      int M, int N, int K, int outMode)
{
    extern __shared__ uint32_t sm4[];
    const uint32_t sb = smem_u32(sm4);

    const int tid  = threadIdx.x;
    const int lane = tid & 31;
    const int w    = tid >> 5;
    const int m0   = blockIdx.y * 128;
    const int n0   = blockIdx.x * 128;
    const int mb   = (w & 1) * 64;
    const int nb   = (w >> 1) * 32;
    const int g    = lane >> 2;
    const int q    = lane & 3;
    const int Kw   = K >> 1;

    float acc[4][4][4];
#pragma unroll
    for (int mt = 0; mt < 4; mt++)
#pragma unroll
        for (int nt = 0; nt < 4; nt++)
#pragma unroll
            for (int i = 0; i < 4; i++) acc[mt][nt][i] = 0.0f;

    // prefetch: 3 arrays x 128 rows x 8 16B-segments = 3072 cp.async / 256 thr
    auto do_prefetch = [&](int c, int st) {
        const uint32_t dbase = sb + (uint32_t)st * STG5 * 4;
        const int bk = c * 32;                    // word offset in K
#pragma unroll
        for (int p = 0; p < 4; p++) {
            int idx = tid + p * 256;              // 0..1023
            int row = idx >> 3;                   // 0..127
            int seg = (idx & 7) * 4;              // word offset 0..28
            size_t soA = (size_t)(m0 + row) * Kw + bk + seg;
            size_t soB = (size_t)(n0 + row) * Kw + bk + seg;
            uint32_t d = dbase + (uint32_t)(row * SPW + seg) * 4;
            CPA16(d,                Ah  + soA);
            CPA16(d + ARR2 * 4,     Bth + soB);
            CPA16(d + 2 * ARR2 * 4, Btl + soB);
        }
        CPA_COMMIT();
    };

    const uint32_t a_rw = (uint32_t)((mb + (lane & 15)) * SPW + ((lane >> 4) << 2));
    const uint32_t b_rw = (uint32_t)((nb + (lane & 7) + ((lane >> 4) << 3)) * SPW
                                     + (((lane >> 3) & 1) << 2));

    const int nch = K >> 6;
    do_prefetch(0, 0);
    for (int c = 0; c < nch; c++) {
        CPA_WAIT0();
        __syncthreads();
        if (c + 1 < nch) do_prefetch(c + 1, (c + 1) & 1);

        const uint32_t ab = sb + (uint32_t)(c & 1) * STG5 * 4;
#pragma unroll
        for (int ks = 0; ks < 4; ks++) {
            const uint32_t aA = ab + (a_rw + ks * 8) * 4;
            const uint32_t bB = ab + (ARR2 + b_rw + ks * 8) * 4;
            uint32_t a[4][4], b_hi[4][2], b_lo[4][2];
#pragma unroll
            for (int mt = 0; mt < 4; mt++)
                LDSM4(a[mt][0], a[mt][1], a[mt][2], a[mt][3],
                      aA + mt * 16 * SPW * 4);
#pragma unroll
            for (int np = 0; np < 2; np++)
                LDSM4(b_hi[2 * np][0], b_hi[2 * np][1],
                      b_hi[2 * np + 1][0], b_hi[2 * np + 1][1],
                      bB + np * 16 * SPW * 4);
#pragma unroll
            for (int mt = 0; mt < 4; mt++)
#pragma unroll
                for (int nt = 0; nt < 4; nt++)
                    MMA_F16(acc[mt][nt], a[mt], b_hi[nt]);
#pragma unroll
            for (int np = 0; np < 2; np++)
                LDSM4(b_lo[2 * np][0], b_lo[2 * np][1],
                      b_lo[2 * np + 1][0], b_lo[2 * np + 1][1],
                      bB + (ARR2 + np * 16 * SPW) * 4);
#pragma unroll
            for (int mt = 0; mt < 4; mt++)
#pragma unroll
                for (int nt = 0; nt < 4; nt++)
                    MMA_F16(acc[mt][nt], a[mt], b_lo[nt]);
        }
    }

    const int Nw = N >> 1;
#pragma unroll
    for (int mt = 0; mt < 4; mt++) {
        int row = m0 + mb + mt * 16 + g;
#pragma unroll
        for (int nt = 0; nt < 4; nt++) {
            int col = n0 + nb + nt * 8 + 2 * q;
            float2 bv = *(const float2*)&bias[col];
            float c0 = acc[mt][nt][0] + bv.x, c1 = acc[mt][nt][1] + bv.y;
            float c2 = acc[mt][nt][2] + bv.x, c3 = acc[mt][nt][3] + bv.y;
            if (outMode) {
                size_t w0 = (size_t)row * Nw + (col >> 1);
                size_t w1 = (size_t)(row + 8) * Nw + (col >> 1);
                uint32_t hA, hB, lA, lB;
                F16X2(hA, c1, c0);
                F16X2(hB, c3, c2);
                __half2 ha = *(__half2*)&hA;
                __half2 hb = *(__half2*)&hB;
                float r0 = c0 - __low2float(ha), r1 = c1 - __high2float(ha);
                float r2 = c2 - __low2float(hb), r3 = c3 - __high2float(hb);
                F16X2(lA, r1, r0);
                F16X2(lB, r3, r2);
                Ch[w0] = hA; Cl[w0] = lA;
                Ch[w1] = hB; Cl[w1] = lB;
            } else {
                *(float2*)&Cf[(size_t)row * N + col]       = make_float2(c0, c1);
                *(float2*)&Cf[(size_t)(row + 8) * N + col] = make_float2(c2, c3);
            }
        }
    }
}

// ---------------------------------------------------------------------------
// MMA flash-attention (causal), fp16, cp.async double-buffered, ldmatrix frags.
// QK^T: q_hi * (k_hi + k_lo).   PV: fp16(P) * v_hi (single product).
// q-tiles processed in DESCENDING order (heaviest CTAs first).
// (unchanged from round 13)
// ---------------------------------------------------------------------------
#define AST 6912
#define A_BYTES (2 * AST * 4)    // 55296

__global__ __launch_bounds__(256, 2)
void attn_mma_kernel(const __half* __restrict__ qkvh_,
                     const __half* __restrict__ qkvl_,
                     __half* __restrict__ yh_)
{
    extern __shared__ uint32_t sma[];
    const uint32_t sb = smem_u32(sma);

    const uint32_t* qh32 = (const uint32_t*)qkvh_;
    const uint32_t* ql32 = (const uint32_t*)qkvl_;
    uint32_t* yh32 = (uint32_t*)yh_;

    const int tid  = threadIdx.x;
    const int lane = tid & 31;
    const int w    = tid >> 5;
    const int g    = lane >> 2;
    const int q    = lane & 3;
    const int bh   = blockIdx.y;
    const int b    = bh >> 4;
    const int h    = bh & 15;
    const int qt   = gridDim.x - 1 - blockIdx.x;   // heavy tiles first
    const int q0   = qt * 128;
    const float scale = 0.125f;

    const size_t base = (size_t)(b * Tq) * 1536;
    const int ktmax = 2 * (qt + 1);

    auto prefetch = [&](int kt, int st) {
        const uint32_t dstg = sb + (uint32_t)st * AST * 4;
#pragma unroll
        for (int p = 0; p < 2; p++) {
            int linear = tid + p * 256;
            int row = linear >> 3;
            int seg = (linear & 7) * 4;
            size_t gk = base + (size_t)(64 * kt + row) * 1536 + 512 + h * 32 + seg;
            size_t gv = gk + 512;
            uint32_t d = dstg + (uint32_t)(row * 36 + seg) * 4;
            CPA16(d,            qh32 + gk);
            CPA16(d + 2304 * 4, ql32 + gk);
            CPA16(d + 4608 * 4, qh32 + gv);
        }
        CPA_COMMIT();
    };

    prefetch(0, 0);

    {
        int row = tid >> 3;
        int j4  = (tid & 7) * 4;
#pragma unroll
        for (int p = 0; p < 4; p++) {
            int r = row + 32 * p;
            size_t gw = base + (size_t)(q0 + r) * 1536 + h * 32 + j4;
            *(uint4*)&sma[AST + r * 36 + j4] = *(const uint4*)(qh32 + gw);
        }
    }
    __syncthreads();
    uint32_t qa[4][4];
    {
        const uint32_t aA = sb + (uint32_t)(AST + (16 * w + (lane & 15)) * 36
                                            + ((lane >> 4) << 2)) * 4;
#pragma unroll
        for (int ks = 0; ks < 4; ks++)
            LDSM4(qa[ks][0], qa[ks][1], qa[ks][2], qa[ks][3], aA + ks * 8 * 4);
    }

    float mrow[2] = {-1e30f, -1e30f};
    float lrow[2] = {0.0f, 0.0f};
    float acc[8][4];
#pragma unroll
    for (int nt = 0; nt < 8; nt++)
#pragma unroll
        for (int i = 0; i < 4; i++) acc[nt][i] = 0.0f;

    const uint32_t k_rw = (uint32_t)(((lane & 7) + ((lane >> 4) << 3)) * 36
                                     + (((lane >> 3) & 1) << 2));
    const uint32_t v_rw = (uint32_t)((lane & 15) * 36 + ((lane >> 4) << 2));

    for (int kt = 0; kt < ktmax; kt++) {
        const int st = kt & 1;
        CPA_WAIT0();
        __syncthreads();
        if (kt + 1 < ktmax) prefetch(kt + 1, st ^ 1);

        if (64 * kt > q0 + 16 * w + 15) continue;

        const uint32_t stb = sb + (uint32_t)st * AST * 4;

        float s[8][4];
#pragma unroll
        for (int nt = 0; nt < 8; nt++)
#pragma unroll
            for (int i = 0; i < 4; i++) s[nt][i] = 0.0f;

#pragma unroll
        for (int ks = 0; ks < 4; ks++) {
            const uint32_t kb_base = stb + (k_rw + ks * 8) * 4;
            uint32_t kb[8][2];
#pragma unroll
            for (int n2 = 0; n2 < 4; n2++)
                LDSM4(kb[2 * n2][0], kb[2 * n2][1],
                      kb[2 * n2 + 1][0], kb[2 * n2 + 1][1],
                      kb_base + n2 * 16 * 36 * 4);
#pragma unroll
            for (int nt = 0; nt < 8; nt++)
                MMA_F16(s[nt], qa[ks], kb[nt]);
#pragma unroll
            for (int n2 = 0; n2 < 4; n2++)
                LDSM4(kb[2 * n2][0], kb[2 * n2][1],
                      kb[2 * n2 + 1][0], kb[2 * n2 + 1][1],
                      kb_base + (2304 + n2 * 16 * 36) * 4);
#pragma unroll
            for (int nt = 0; nt < 8; nt++)
                MMA_F16(s[nt], qa[ks], kb[nt]);
        }

        const int rowa = q0 + 16 * w + g;
        const int rowb = rowa + 8;
        const bool domask = (64 * kt + 63 > rowa);
#pragma unroll
        for (int nt = 0; nt < 8; nt++) {
#pragma unroll
            for (int i = 0; i < 4; i++) s[nt][i] *= scale;
            if (domask) {
                int kbase = 64 * kt + 8 * nt + 2 * q;
                if (kbase     > rowa) s[nt][0] = -1e30f;
                if (kbase + 1 > rowa) s[nt][1] = -1e30f;
                if (kbase     > rowb) s[nt][2] = -1e30f;
                if (kbase + 1 > rowb) s[nt][3] = -1e30f;
            }
        }

#pragma unroll
        for (int r = 0; r < 2; r++) {
            float mx = -1e30f;
#pragma unroll
            for (int nt = 0; nt < 8; nt++)
                mx = fmaxf(mx, fmaxf(s[nt][2 * r], s[nt][2 * r + 1]));
            mx = fmaxf(mx, __shfl_xor_sync(0xffffffffu, mx, 1));
            mx = fmaxf(mx, __shfl_xor_sync(0xffffffffu, mx, 2));
            float mnew  = fmaxf(mrow[r], mx);
            float alpha = __expf(mrow[r] - mnew);
            float sum = 0.0f;
#pragma unroll
            for (int nt = 0; nt < 8; nt++) {
                s[nt][2 * r]     = __expf(s[nt][2 * r]     - mnew);
                s[nt][2 * r + 1] = __expf(s[nt][2 * r + 1] - mnew);
                sum += s[nt][2 * r] + s[nt][2 * r + 1];
            }
            sum += __shfl_xor_sync(0xffffffffu, sum, 1);
            sum += __shfl_xor_sync(0xffffffffu, sum, 2);
            lrow[r] = lrow[r] * alpha + sum;
            mrow[r] = mnew;
#pragma unroll
            for (int nt = 0; nt < 8; nt++) {
                acc[nt][2 * r]     *= alpha;
                acc[nt][2 * r + 1] *= alpha;
            }
        }

#pragma unroll
        for (int t = 0; t < 4; t++) {
            uint32_t ph[4];
            F16X2(ph[0], s[2*t][1],   s[2*t][0]);
            F16X2(ph[1], s[2*t][3],   s[2*t][2]);
            F16X2(ph[2], s[2*t+1][1], s[2*t+1][0]);
            F16X2(ph[3], s[2*t+1][3], s[2*t+1][2]);
            const uint32_t vb_base = stb + (v_rw + t * 16 * 36) * 4;
            uint32_t vb[8][2];
#pragma unroll
            for (int g2 = 0; g2 < 4; g2++)
                LDSM4T(vb[2 * g2][0], vb[2 * g2][1],
                       vb[2 * g2 + 1][0], vb[2 * g2 + 1][1],
                       vb_base + (4608 + g2 * 8) * 4);
#pragma unroll
            for (int nt = 0; nt < 8; nt++)
                MMA_F16(acc[nt], ph, vb[nt]);
        }
    }

    {
        float inv0 = 1.0f / lrow[0];
        float inv1 = 1.0f / lrow[1];
        int r = q0 + 16 * w + g;
        size_t w0b = ((size_t)(b * Tq) + r) * 512 + h * 32 + q;
        size_t w1b = w0b + (size_t)8 * 512;
#pragma unroll
        for (int nt = 0; nt < 8; nt++) {
            float v0 = acc[nt][0] * inv0, v1 = acc[nt][1] * inv0;
            float v2 = acc[nt][2] * inv1, v3 = acc[nt][3] * inv1;
            uint32_t o0, o1;
            F16X2(o0, v1, v0);
            F16X2(o1, v3, v2);
            yh32[w0b + 4 * nt] = o0;
            yh32[w1b + 4 * nt] = o1;
        }
    }
}

// ---------------------------------------------------------------------------
// Launch
// ---------------------------------------------------------------------------
extern "C" void kernel_launch(void* const* d_in, const int* in_sizes, int n_in,
                              void* d_out, int out_size)
{
    (void)in_sizes; (void)n_in; (void)out_size;
    const float* x      = (const float*)d_in[0];
    const float* W_attn = (const float*)d_in[1];
    const float* b_attn = (const float*)d_in[2];
    const float* W_proj = (const float*)d_in[3];
    const float* b_proj = (const float*)d_in[4];
    float* out = (float*)d_out;

    __half *x16, *wqh, *wql, *wph, *wpl, *qh, *ql, *yh;
    cudaGetSymbolAddress((void**)&x16, g_x16);
    cudaGetSymbolAddress((void**)&wqh, g_wqh);
    cudaGetSymbolAddress((void**)&wql, g_wql);
    cudaGetSymbolAddress((void**)&wph, g_wph);
    cudaGetSymbolAddress((void**)&wpl, g_wpl);
    cudaGetSymbolAddress((void**)&qh,  g_qkvh);
    cudaGetSymbolAddress((void**)&ql,  g_qkvl);
    cudaGetSymbolAddress((void**)&yh,  g_yh);

    cudaFuncSetAttribute(gemm_mma4_kernel,
                         cudaFuncAttributeMaxDynamicSharedMemorySize, G4_BYTES);
    cudaFuncSetAttribute(attn_mma_kernel,
                         cudaFuncAttributeMaxDynamicSharedMemorySize, A_BYTES);

    // 0) pre-convert operands
    cvt_f16_kernel<<<(MQ * Cq / 4 + 255) / 256, 256>>>(x, x16, MQ * Cq / 4);
    cvt_splitT_f16_kernel<<<dim3(C3 / 32, Cq / 32), 256>>>(W_attn, wqh, wql, Cq, C3);
    cvt_splitT_f16_kernel<<<dim3(Cq / 32, Cq / 32), 256>>>(W_proj, wph, wpl, Cq, Cq);

    // 1) qkv(fp16 hi/lo) = x @ W_attn + b_attn
    gemm_mma4_kernel<<<dim3(C3 / 128, MQ / 128), 256, G4_BYTES>>>(
        (const uint32_t*)x16,
        (const uint32_t*)wqh, (const uint32_t*)wql,
        b_attn, nullptr, (uint32_t*)qh, (uint32_t*)ql, MQ, C3, Cq, 1);

    // 2) y(fp16) = causal_attention(qkv)
    attn_mma_kernel<<<dim3(Tq / 128, Bq * NH), 256, A_BYTES>>>(qh, ql, yh);

    // 3) out(fp32) = y @ W_proj + b_proj
    gemm_mma4_kernel<<<dim3(Cq / 128, MQ / 128), 256, G4_BYTES>>>(
        (const uint32_t*)yh,
        (const uint32_t*)wph, (const uint32_t*)wpl,
        b_proj, out, nullptr, nullptr, MQ, Cq, Cq, 0);
}

// round 15
// speedup vs baseline: 5.3493x; 1.1133x over previous
#include <cuda_runtime.h>
#include <cuda_bf16.h>
#include <cuda_fp16.h>
#include <math.h>
#include <stdint.h>

// Problem constants
#define Bq   4
#define Tq   2048
#define Cq   1024
#define NH   16
#define HD   64
#define C3   (3 * Cq)          // 3072
#define MQ   (Bq * Tq)         // 8192 rows

// ---------------------------------------------------------------------------
// Scratch (device globals; no runtime allocation allowed)
// ---------------------------------------------------------------------------
__device__ __align__(128) __half g_x16 [(size_t)MQ * Cq];    // x, fp16
__device__ __align__(128) __half g_wqh [(size_t)C3 * Cq];    // W_attn^T hi
__device__ __align__(128) __half g_wql [(size_t)C3 * Cq];    // W_attn^T lo
__device__ __align__(128) __half g_wph [(size_t)Cq * Cq];    // W_proj^T hi
__device__ __align__(128) __half g_wpl [(size_t)Cq * Cq];    // W_proj^T lo
__device__ __align__(128) __half g_qkvh[(size_t)MQ * C3];    // qkv (single fp16)
__device__ __align__(128) __half g_yh  [(size_t)MQ * Cq];    // attn out, fp16

// ---------------------------------------------------------------------------
// helpers
// ---------------------------------------------------------------------------
__device__ __forceinline__ uint32_t smem_u32(const void* p) {
    uint32_t a;
    asm("{ .reg .u64 t; cvta.to.shared.u64 t, %1; cvt.u32.u64 %0, t; }"
        : "=r"(a) : "l"(p));
    return a;
}

#define MMA_F16(d, av, bv)                                                     \
  asm volatile("mma.sync.aligned.m16n8k16.row.col.f32.f16.f16.f32 "            \
      "{%0,%1,%2,%3}, {%4,%5,%6,%7}, {%8,%9}, {%0,%1,%2,%3};"                  \
      : "+f"((d)[0]), "+f"((d)[1]), "+f"((d)[2]), "+f"((d)[3])                 \
      : "r"((av)[0]), "r"((av)[1]), "r"((av)[2]), "r"((av)[3]),                \
        "r"((bv)[0]), "r"((bv)[1]))

#define LDSM4(R0, R1, R2, R3, A)                                               \
  asm volatile("ldmatrix.sync.aligned.m8n8.x4.shared.b16 {%0,%1,%2,%3}, [%4];" \
      : "=r"(R0), "=r"(R1), "=r"(R2), "=r"(R3) : "r"(A))

#define LDSM4T(R0, R1, R2, R3, A)                                              \
  asm volatile("ldmatrix.sync.aligned.m8n8.x4.trans.shared.b16 {%0,%1,%2,%3}, [%4];" \
      : "=r"(R0), "=r"(R1), "=r"(R2), "=r"(R3) : "r"(A))

#define CPA16(dst, src)                                                        \
  asm volatile("cp.async.cg.shared.global [%0], [%1], 16;"                     \
      :: "r"(dst), "l"(src) : "memory")
#define CPA_COMMIT() asm volatile("cp.async.commit_group;" ::: "memory")
#define CPA_WAIT0()  asm volatile("cp.async.wait_group 0;" ::: "memory")

#define F16X2(dst, hi_f, lo_f)                                                 \
  asm("cvt.rn.f16x2.f32 %0, %1, %2;" : "=r"(dst) : "f"(hi_f), "f"(lo_f))

// ---------------------------------------------------------------------------
// cvt kernels
// ---------------------------------------------------------------------------
__global__ void cvt_f16_kernel(const float* __restrict__ a,
                               __half* __restrict__ o, int n4)
{
    int i = blockIdx.x * 256 + threadIdx.x;
    if (i >= n4) return;
    float4 v = ((const float4*)a)[i];
    uint32_t w0, w1;
    F16X2(w0, v.y, v.x);
    F16X2(w1, v.w, v.z);
    uint32_t* o32 = (uint32_t*)o;
    o32[2 * i + 0] = w0;
    o32[2 * i + 1] = w1;
}

// W[K][N] -> out[N][K] fp16 hi/lo
__global__ void cvt_splitT_f16_kernel(const float* __restrict__ w,
                                      __half* __restrict__ th,
                                      __half* __restrict__ tl, int K, int N)
{
    __shared__ float t[32][33];
    int tx = threadIdx.x & 31, ty = threadIdx.x >> 5;
    int k0 = blockIdx.y * 32, n0 = blockIdx.x * 32;
#pragma unroll
    for (int r = 0; r < 4; r++)
        t[ty + 8 * r][tx] = w[(size_t)(k0 + ty + 8 * r) * N + n0 + tx];
    __syncthreads();
#pragma unroll
    for (int r = 0; r < 4; r++) {
        int n = n0 + ty + 8 * r;
        float v = t[tx][ty + 8 * r];
        __half hh = __float2half_rn(v);
        th[(size_t)n * K + k0 + tx] = hh;
        tl[(size_t)n * K + k0 + tx] = __float2half_rn(v - __half2float(hh));
    }
}

// ---------------------------------------------------------------------------
// Pipelined warp-MMA GEMM: C = A[M,K] @ (Bth+Btl)^T + bias   (all fp16 in)
// K-chunk 64 (4 k16-steps), 2-stage cp.async, ONE __syncthreads per chunk.
// All fragment LDSMs hoisted to the top of each ks-step.
// outMode 0: fp32 Cf.  outMode 1: single fp16 (Ch word array).
// ---------------------------------------------------------------------------
#define SPW  36                  // words per smem row (32 data + 4 pad)
#define ARR2 4608                // words per array (128*36)
#define STG5 13824               // words per stage (3 arrays)
#define G4_BYTES (2 * STG5 * 4)  // 110592

__global__ __launch_bounds__(256, 2)
void gemm_mma4_kernel(const uint32_t* __restrict__ Ah,
                      const uint32_t* __restrict__ Bth, const uint32_t* __restrict__ Btl,
                      const float* __restrict__ bias, float* __restrict__ Cf,
                      uint32_t* __restrict__ Ch,
                      int M, int N, int K, int outMode)
{
    extern __shared__ uint32_t sm4[];
    const uint32_t sb = smem_u32(sm4);

    const int tid  = threadIdx.x;
    const int lane = tid & 31;
    const int w    = tid >> 5;
    const int m0   = blockIdx.y * 128;
    const int n0   = blockIdx.x * 128;
    const int mb   = (w & 1) * 64;
    const int nb   = (w >> 1) * 32;
    const int g    = lane >> 2;
    const int q    = lane & 3;
    const int Kw   = K >> 1;

    float acc[4][4][4];
#pragma unroll
    for (int mt = 0; mt < 4; mt++)
#pragma unroll
        for (int nt = 0; nt < 4; nt++)
#pragma unroll
            for (int i = 0; i < 4; i++) acc[mt][nt][i] = 0.0f;

    auto do_prefetch = [&](int c, int st) {
        const uint32_t dbase = sb + (uint32_t)st * STG5 * 4;
        const int bk = c * 32;
#pragma unroll
        for (int p = 0; p < 4; p++) {
            int idx = tid + p * 256;
            int row = idx >> 3;
            int seg = (idx & 7) * 4;
            size_t soA = (size_t)(m0 + row) * Kw + bk + seg;
            size_t soB = (size_t)(n0 + row) * Kw + bk + seg;
            uint32_t d = dbase + (uint32_t)(row * SPW + seg) * 4;
            CPA16(d,                Ah  + soA);
            CPA16(d + ARR2 * 4,     Bth + soB);
            CPA16(d + 2 * ARR2 * 4, Btl + soB);
        }
        CPA_COMMIT();
    };

    const uint32_t a_rw = (uint32_t)((mb + (lane & 15)) * SPW + ((lane >> 4) << 2));
    const uint32_t b_rw = (uint32_t)((nb + (lane & 7) + ((lane >> 4) << 3)) * SPW
                                     + (((lane >> 3) & 1) << 2));

    const int nch = K >> 6;
    do_prefetch(0, 0);
    for (int c = 0; c < nch; c++) {
        CPA_WAIT0();
        __syncthreads();
        if (c + 1 < nch) do_prefetch(c + 1, (c + 1) & 1);

        const uint32_t ab = sb + (uint32_t)(c & 1) * STG5 * 4;
#pragma unroll
        for (int ks = 0; ks < 4; ks++) {
            const uint32_t aA = ab + (a_rw + ks * 8) * 4;
            const uint32_t bB = ab + (ARR2 + b_rw + ks * 8) * 4;
            uint32_t a[4][4], b_hi[4][2], b_lo[4][2];
            // --- all fragment loads up front ---
#pragma unroll
            for (int mt = 0; mt < 4; mt++)
                LDSM4(a[mt][0], a[mt][1], a[mt][2], a[mt][3],
                      aA + mt * 16 * SPW * 4);
#pragma unroll
            for (int np = 0; np < 2; np++)
                LDSM4(b_hi[2 * np][0], b_hi[2 * np][1],
                      b_hi[2 * np + 1][0], b_hi[2 * np + 1][1],
                      bB + np * 16 * SPW * 4);
#pragma unroll
            for (int np = 0; np < 2; np++)
                LDSM4(b_lo[2 * np][0], b_lo[2 * np][1],
                      b_lo[2 * np + 1][0], b_lo[2 * np + 1][1],
                      bB + (ARR2 + np * 16 * SPW) * 4);
            // --- MMAs ---
#pragma unroll
            for (int mt = 0; mt < 4; mt++)
#pragma unroll
                for (int nt = 0; nt < 4; nt++)
                    MMA_F16(acc[mt][nt], a[mt], b_hi[nt]);
#pragma unroll
            for (int mt = 0; mt < 4; mt++)
#pragma unroll
                for (int nt = 0; nt < 4; nt++)
                    MMA_F16(acc[mt][nt], a[mt], b_lo[nt]);
        }
    }

    const int Nw = N >> 1;
#pragma unroll
    for (int mt = 0; mt < 4; mt++) {
        int row = m0 + mb + mt * 16 + g;
#pragma unroll
        for (int nt = 0; nt < 4; nt++) {
            int col = n0 + nb + nt * 8 + 2 * q;
            float2 bv = *(const float2*)&bias[col];
            float c0 = acc[mt][nt][0] + bv.x, c1 = acc[mt][nt][1] + bv.y;
            float c2 = acc[mt][nt][2] + bv.x, c3 = acc[mt][nt][3] + bv.y;
            if (outMode) {
                size_t w0 = (size_t)row * Nw + (col >> 1);
                size_t w1 = (size_t)(row + 8) * Nw + (col >> 1);
                uint32_t hA, hB;
                F16X2(hA, c1, c0);
                F16X2(hB, c3, c2);
                Ch[w0] = hA;
                Ch[w1] = hB;
            } else {
                *(float2*)&Cf[(size_t)row * N + col]       = make_float2(c0, c1);
                *(float2*)&Cf[(size_t)(row + 8) * N + col] = make_float2(c2, c3);
            }
        }
    }
}

// ---------------------------------------------------------------------------
// MMA flash-attention (causal), fp16 single-precision operands throughout.
// QK^T: q * k (single product).  PV: fp16(P) * v (single product).
// cp.async double-buffered K/V tiles, ldmatrix frags, descending q-tile order.
// ---------------------------------------------------------------------------
// per-stage smem (words): Kh 0, Vh 2304   ([64][36] each)
#define AST2 4608
#define A_BYTES ((2 * AST2 + 4608) * 4)   // 2 stages + Q staging = 55296

__global__ __launch_bounds__(256, 2)
void attn_mma_kernel(const __half* __restrict__ qkvh_,
                     __half* __restrict__ yh_)
{
    extern __shared__ uint32_t sma[];
    const uint32_t sb = smem_u32(sma);

    const uint32_t* qh32 = (const uint32_t*)qkvh_;
    uint32_t* yh32 = (uint32_t*)yh_;

    const int tid  = threadIdx.x;
    const int lane = tid & 31;
    const int w    = tid >> 5;
    const int g    = lane >> 2;
    const int q    = lane & 3;
    const int bh   = blockIdx.y;
    const int b    = bh >> 4;
    const int h    = bh & 15;
    const int qt   = gridDim.x - 1 - blockIdx.x;   // heavy tiles first
    const int q0   = qt * 128;
    const float scale = 0.125f;

    const size_t base = (size_t)(b * Tq) * 1536;
    const int ktmax = 2 * (qt + 1);

    // prefetch K + V tile kt into stage st (4 cp.async per thread)
    auto prefetch = [&](int kt, int st) {
        const uint32_t dstg = sb + (uint32_t)st * AST2 * 4;
#pragma unroll
        for (int p = 0; p < 2; p++) {
            int linear = tid + p * 256;
            int row = linear >> 3;
            int seg = (linear & 7) * 4;
            size_t gk = base + (size_t)(64 * kt + row) * 1536 + 512 + h * 32 + seg;
            size_t gv = gk + 512;
            uint32_t d = dstg + (uint32_t)(row * 36 + seg) * 4;
            CPA16(d,            qh32 + gk);      // K
            CPA16(d + 2304 * 4, qh32 + gv);      // V
        }
        CPA_COMMIT();
    };

    prefetch(0, 0);

    // ---- stage Q into region above both stages, build register fragments ----
    {
        int row = tid >> 3;
        int j4  = (tid & 7) * 4;
#pragma unroll
        for (int p = 0; p < 4; p++) {
            int r = row + 32 * p;
            size_t gw = base + (size_t)(q0 + r) * 1536 + h * 32 + j4;
            *(uint4*)&sma[2 * AST2 + r * 36 + j4] = *(const uint4*)(qh32 + gw);
        }
    }
    __syncthreads();
    uint32_t qa[4][4];
    {
        const uint32_t aA = sb + (uint32_t)(2 * AST2 + (16 * w + (lane & 15)) * 36
                                            + ((lane >> 4) << 2)) * 4;
#pragma unroll
        for (int ks = 0; ks < 4; ks++)
            LDSM4(qa[ks][0], qa[ks][1], qa[ks][2], qa[ks][3], aA + ks * 8 * 4);
    }

    float mrow[2] = {-1e30f, -1e30f};
    float lrow[2] = {0.0f, 0.0f};
    float acc[8][4];
#pragma unroll
    for (int nt = 0; nt < 8; nt++)
#pragma unroll
        for (int i = 0; i < 4; i++) acc[nt][i] = 0.0f;

    const uint32_t k_rw = (uint32_t)(((lane & 7) + ((lane >> 4) << 3)) * 36
                                     + (((lane >> 3) & 1) << 2));
    const uint32_t v_rw = (uint32_t)((lane & 15) * 36 + ((lane >> 4) << 2));

    for (int kt = 0; kt < ktmax; kt++) {
        const int st = kt & 1;
        CPA_WAIT0();
        __syncthreads();
        if (kt + 1 < ktmax) prefetch(kt + 1, st ^ 1);

        if (64 * kt > q0 + 16 * w + 15) continue;   // warp tile fully masked

        const uint32_t stb = sb + (uint32_t)st * AST2 * 4;

        // ---- S = Q K^T (single product) ----
        float s[8][4];
#pragma unroll
        for (int nt = 0; nt < 8; nt++)
#pragma unroll
            for (int i = 0; i < 4; i++) s[nt][i] = 0.0f;

#pragma unroll
        for (int ks = 0; ks < 4; ks++) {
            const uint32_t kb_base = stb + (k_rw + ks * 8) * 4;
            uint32_t kb[8][2];
#pragma unroll
            for (int n2 = 0; n2 < 4; n2++)
                LDSM4(kb[2 * n2][0], kb[2 * n2][1],
                      kb[2 * n2 + 1][0], kb[2 * n2 + 1][1],
                      kb_base + n2 * 16 * 36 * 4);
#pragma unroll
            for (int nt = 0; nt < 8; nt++)
                MMA_F16(s[nt], qa[ks], kb[nt]);
        }

        // ---- scale + causal mask ----
        const int rowa = q0 + 16 * w + g;
        const int rowb = rowa + 8;
        const bool domask = (64 * kt + 63 > rowa);
#pragma unroll
        for (int nt = 0; nt < 8; nt++) {
#pragma unroll
            for (int i = 0; i < 4; i++) s[nt][i] *= scale;
            if (domask) {
                int kbase = 64 * kt + 8 * nt + 2 * q;
                if (kbase     > rowa) s[nt][0] = -1e30f;
                if (kbase + 1 > rowa) s[nt][1] = -1e30f;
                if (kbase     > rowb) s[nt][2] = -1e30f;
                if (kbase + 1 > rowb) s[nt][3] = -1e30f;
            }
        }

        // ---- online softmax ----
#pragma unroll
        for (int r = 0; r < 2; r++) {
            float mx = -1e30f;
#pragma unroll
            for (int nt = 0; nt < 8; nt++)
                mx = fmaxf(mx, fmaxf(s[nt][2 * r], s[nt][2 * r + 1]));
            mx = fmaxf(mx, __shfl_xor_sync(0xffffffffu, mx, 1));
            mx = fmaxf(mx, __shfl_xor_sync(0xffffffffu, mx, 2));
            float mnew  = fmaxf(mrow[r], mx);
            float alpha = __expf(mrow[r] - mnew);
            float sum = 0.0f;
#pragma unroll
            for (int nt = 0; nt < 8; nt++) {
                s[nt][2 * r]     = __expf(s[nt][2 * r]     - mnew);
                s[nt][2 * r + 1] = __expf(s[nt][2 * r + 1] - mnew);
                sum += s[nt][2 * r] + s[nt][2 * r + 1];
            }
            sum += __shfl_xor_sync(0xffffffffu, sum, 1);
            sum += __shfl_xor_sync(0xffffffffu, sum, 2);
            lrow[r] = lrow[r] * alpha + sum;
            mrow[r] = mnew;
#pragma unroll
            for (int nt = 0; nt < 8; nt++) {
                acc[nt][2 * r]     *= alpha;
                acc[nt][2 * r + 1] *= alpha;
            }
        }

        // ---- PV: fp16(P) x V (single product); V via ldmatrix.trans ----
#pragma unroll
        for (int t = 0; t < 4; t++) {
            uint32_t ph[4];
            F16X2(ph[0], s[2*t][1],   s[2*t][0]);
            F16X2(ph[1], s[2*t][3],   s[2*t][2]);
            F16X2(ph[2], s[2*t+1][1], s[2*t+1][0]);
            F16X2(ph[3], s[2*t+1][3], s[2*t+1][2]);
            const uint32_t vb_base = stb + (v_rw + t * 16 * 36) * 4;
            uint32_t vb[8][2];
#pragma unroll
            for (int g2 = 0; g2 < 4; g2++)
                LDSM4T(vb[2 * g2][0], vb[2 * g2][1],
                       vb[2 * g2 + 1][0], vb[2 * g2 + 1][1],
                       vb_base + (2304 + g2 * 8) * 4);
#pragma unroll
            for (int nt = 0; nt < 8; nt++)
                MMA_F16(acc[nt], ph, vb[nt]);
        }
    }

    // ---- epilogue: normalize, single-fp16 store of y ----
    {
        float inv0 = 1.0f / lrow[0];
        float inv1 = 1.0f / lrow[1];
        int r = q0 + 16 * w + g;
        size_t w0b = ((size_t)(b * Tq) + r) * 512 + h * 32 + q;
        size_t w1b = w0b + (size_t)8 * 512;
#pragma unroll
        for (int nt = 0; nt < 8; nt++) {
            float v0 = acc[nt][0] * inv0, v1 = acc[nt][1] * inv0;
            float v2 = acc[nt][2] * inv1, v3 = acc[nt][3] * inv1;
            uint32_t o0, o1;
            F16X2(o0, v1, v0);
            F16X2(o1, v3, v2);
            yh32[w0b + 4 * nt] = o0;
            yh32[w1b + 4 * nt] = o1;
        }
    }
}

// ---------------------------------------------------------------------------
// Launch
// ---------------------------------------------------------------------------
extern "C" void kernel_launch(void* const* d_in, const int* in_sizes, int n_in,
                              void* d_out, int out_size)
{
    (void)in_sizes; (void)n_in; (void)out_size;
    const float* x      = (const float*)d_in[0];
    const float* W_attn = (const float*)d_in[1];
    const float* b_attn = (const float*)d_in[2];
    const float* W_proj = (const float*)d_in[3];
    const float* b_proj = (const float*)d_in[4];
    float* out = (float*)d_out;

    __half *x16, *wqh, *wql, *wph, *wpl, *qh, *yh;
    cudaGetSymbolAddress((void**)&x16, g_x16);
    cudaGetSymbolAddress((void**)&wqh, g_wqh);
    cudaGetSymbolAddress((void**)&wql, g_wql);
    cudaGetSymbolAddress((void**)&wph, g_wph);
    cudaGetSymbolAddress((void**)&wpl, g_wpl);
    cudaGetSymbolAddress((void**)&qh,  g_qkvh);
    cudaGetSymbolAddress((void**)&yh,  g_yh);

    cudaFuncSetAttribute(gemm_mma4_kernel,
                         cudaFuncAttributeMaxDynamicSharedMemorySize, G4_BYTES);
    cudaFuncSetAttribute(attn_mma_kernel,
                         cudaFuncAttributeMaxDynamicSharedMemorySize, A_BYTES);

    // 0) pre-convert operands
    cvt_f16_kernel<<<(MQ * Cq / 4 + 255) / 256, 256>>>(x, x16, MQ * Cq / 4);
    cvt_splitT_f16_kernel<<<dim3(C3 / 32, Cq / 32), 256>>>(W_attn, wqh, wql, Cq, C3);
    cvt_splitT_f16_kernel<<<dim3(Cq / 32, Cq / 32), 256>>>(W_proj, wph, wpl, Cq, Cq);

    // 1) qkv(fp16) = x @ W_attn + b_attn
    gemm_mma4_kernel<<<dim3(C3 / 128, MQ / 128), 256, G4_BYTES>>>(
        (const uint32_t*)x16,
        (const uint32_t*)wqh, (const uint32_t*)wql,
        b_attn, nullptr, (uint32_t*)qh, MQ, C3, Cq, 1);

    // 2) y(fp16) = causal_attention(qkv)
    attn_mma_kernel<<<dim3(Tq / 128, Bq * NH), 256, A_BYTES>>>(qh, yh);

    // 3) out(fp32) = y @ W_proj + b_proj
    gemm_mma4_kernel<<<dim3(Cq / 128, MQ / 128), 256, G4_BYTES>>>(
        (const uint32_t*)yh,
        (const uint32_t*)wph, (const uint32_t*)wpl,
        b_proj, out, nullptr, MQ, Cq, Cq, 0);
}